// round 3
// baseline (speedup 1.0000x reference)
#include <cuda_runtime.h>
#include <mma.h>
#include <math.h>

using namespace nvcuda;

#define VOCAB 32000
#define EMB   512
#define HID   1024
#define BB    16
#define TT    512
#define H3    3072
#define LDH   1032   // padded smem row

__device__ float g_gi0[(size_t)TT * BB * H3];    // [t][b][3H]
__device__ float g_h0seq[(size_t)TT * BB * HID]; // [t][b][H]
__device__ float g_h1seq[(size_t)BB * TT * HID]; // [b][t][H]
__device__ unsigned g_cnt[2 * TT];

__device__ __forceinline__ float sigmoidf_(float x) { return 1.f / (1.f + expf(-x)); }

__global__ void zero_cnt_k(unsigned* c) {
    int i = blockIdx.x * blockDim.x + threadIdx.x;
    if (i < 2 * TT) c[i] = 0u;
}

__global__ void tail_copy_k(const float* __restrict__ h0seq,
                            const float* __restrict__ h1seq,
                            float* __restrict__ out) {
    int i = blockIdx.x * blockDim.x + threadIdx.x;
    if (i < BB * HID) {
        int b = i >> 10, j = i & 1023;
        out[(size_t)BB * TT * VOCAB + i] =
            h0seq[((size_t)(TT - 1) * BB + b) * HID + j];
        out[(size_t)BB * TT * VOCAB + BB * HID + i] =
            h1seq[((size_t)b * TT + (TT - 1)) * HID + j];
    }
}

// ---------------------------------------------------------------------------
// tf32 WMMA GEMM: C[M,N] = A[M,K] @ B[N,K]^T + bias[N]
// GATHER=1: A row m -> emb[seq[(m&15)*T + (m>>4)]]
// ---------------------------------------------------------------------------
template <int GATHER>
__global__ void __launch_bounds__(256, 1)
gemm_tf32(const float* __restrict__ A, const int* __restrict__ seq,
          const float* __restrict__ Bm, const float* __restrict__ bias,
          float* __restrict__ C, int M, int N, int K, int lda)
{
    __shared__ float As[128][36];
    __shared__ float Bs[128][36];
    __shared__ float biasS[16][136];

    const int tid = threadIdx.x;
    const int m0 = blockIdx.y * 128;
    const int n0 = blockIdx.x * 128;

    for (int i = tid; i < 16 * 128; i += 256)
        biasS[i >> 7][i & 127] = bias[n0 + (i & 127)];
    __syncthreads();

    const int warpId = tid >> 5;
    const int wm = warpId >> 1;   // 0..3
    const int wn = warpId & 1;    // 0..1

    wmma::fragment<wmma::accumulator, 16, 16, 8, float> acc[2][4];
#pragma unroll
    for (int mi = 0; mi < 2; mi++)
#pragma unroll
        for (int ni = 0; ni < 4; ni++)
            wmma::load_matrix_sync(acc[mi][ni], &biasS[0][wn * 64 + ni * 16], 136,
                                   wmma::mem_row_major);

    for (int k0 = 0; k0 < K; k0 += 32) {
#pragma unroll
        for (int i = tid; i < 1024; i += 256) {
            int row = i >> 3, c4 = i & 7;
            int m = m0 + row;
            const float* src;
            if (GATHER) src = A + (size_t)seq[(m & 15) * TT + (m >> 4)] * lda;
            else        src = A + (size_t)m * lda;
            *(float4*)&As[row][c4 * 4] = *(const float4*)(src + k0 + c4 * 4);
            *(float4*)&Bs[row][c4 * 4] =
                *(const float4*)(Bm + (size_t)(n0 + row) * K + k0 + c4 * 4);
        }
        __syncthreads();

#pragma unroll
        for (int ks = 0; ks < 4; ks++) {
            wmma::fragment<wmma::matrix_a, 16, 16, 8, wmma::precision::tf32, wmma::row_major> a[2];
            wmma::fragment<wmma::matrix_b, 16, 16, 8, wmma::precision::tf32, wmma::col_major> b[4];
#pragma unroll
            for (int mi = 0; mi < 2; mi++) {
                wmma::load_matrix_sync(a[mi], &As[wm * 32 + mi * 16][ks * 8], 36);
#pragma unroll
                for (int e = 0; e < a[mi].num_elements; e++)
                    a[mi].x[e] = wmma::__float_to_tf32(a[mi].x[e]);
            }
#pragma unroll
            for (int ni = 0; ni < 4; ni++) {
                wmma::load_matrix_sync(b[ni], &Bs[wn * 64 + ni * 16][ks * 8], 36);
#pragma unroll
                for (int e = 0; e < b[ni].num_elements; e++)
                    b[ni].x[e] = wmma::__float_to_tf32(b[ni].x[e]);
            }
#pragma unroll
            for (int mi = 0; mi < 2; mi++)
#pragma unroll
                for (int ni = 0; ni < 4; ni++)
                    wmma::mma_sync(acc[mi][ni], a[mi], b[ni], acc[mi][ni]);
        }
        __syncthreads();
    }

#pragma unroll
    for (int mi = 0; mi < 2; mi++)
#pragma unroll
        for (int ni = 0; ni < 4; ni++)
            wmma::store_matrix_sync(C + (size_t)(m0 + wm * 32 + mi * 16) * N
                                      + n0 + wn * 64 + ni * 16,
                                    acc[mi][ni], N, wmma::mem_row_major);
}

// ---------------------------------------------------------------------------
// Persistent GRU: 128 CTAs x 256 thr. CTA<64: layer0 (cols cta*16..+16).
// CTA>=64: layer1. Step chaining via L2 counters: cnt[t] (layer0 done),
// cnt[TT+t] (layer1 done). All CTAs co-resident (1 CTA/SM @132KB smem).
// ---------------------------------------------------------------------------
__global__ void __launch_bounds__(256, 1)
gru_persistent(const float* __restrict__ gi0,
               const float* __restrict__ whh0, const float* __restrict__ bhh0,
               const float* __restrict__ wih1, const float* __restrict__ bih1,
               const float* __restrict__ whh1, const float* __restrict__ bhh1,
               float* __restrict__ h0seq, float* __restrict__ h1seq,
               unsigned* __restrict__ cnt)
{
    extern __shared__ float sh[];     // A: h_prev[16][LDH] | B: x[16][LDH], h[16][LDH]
    const int tid = threadIdx.x;
    const bool isA = blockIdx.x < 64;
    const int c0 = (isA ? blockIdx.x : blockIdx.x - 64) * 16;
    const int b = tid & 15, j = c0 + (tid >> 4);
    volatile unsigned* vc = cnt;

    for (int t = 0; t < TT; t++) {
        if (tid == 0) {
            if (isA) { if (t) while (vc[t - 1] < 64u) {} }
            else {
                while (vc[t] < 64u) {}
                if (t) while (vc[TT + t - 1] < 64u) {}
            }
        }
        __syncthreads();
        __threadfence();

        if (isA) {
            if (t == 0) { for (int i = tid; i < 16 * LDH; i += 256) sh[i] = 0.f; }
            else {
                const float4* s = (const float4*)(h0seq + (size_t)(t - 1) * BB * HID);
                for (int i = tid; i < 4096; i += 256)
                    *(float4*)&sh[(i >> 8) * LDH + (i & 255) * 4] = s[i];
            }
        } else {
            const float4* sx = (const float4*)(h0seq + (size_t)t * BB * HID);
            for (int i = tid; i < 4096; i += 256)
                *(float4*)&sh[(i >> 8) * LDH + (i & 255) * 4] = sx[i];
            if (t == 0) { for (int i = tid; i < 16 * LDH; i += 256) sh[16 * LDH + i] = 0.f; }
            else {
                for (int i = tid; i < 4096; i += 256) {
                    int bb = i >> 8, k4 = i & 255;
                    *(float4*)&sh[16 * LDH + bb * LDH + k4 * 4] =
                        *(const float4*)(h1seq + ((size_t)bb * TT + (t - 1)) * HID + k4 * 4);
                }
            }
        }
        __syncthreads();

        if (isA) {
            const float4* hp = (const float4*)(sh + b * LDH);
            const float4* wr = (const float4*)(whh0 + (size_t)j * HID);
            const float4* wu = (const float4*)(whh0 + (size_t)(HID + j) * HID);
            const float4* wn = (const float4*)(whh0 + (size_t)(2 * HID + j) * HID);
            float ar = 0.f, au = 0.f, an = 0.f;
#pragma unroll 8
            for (int k = 0; k < 256; k++) {
                float4 h4 = hp[k], r4 = wr[k], u4 = wu[k], n4 = wn[k];
                ar += h4.x * r4.x + h4.y * r4.y + h4.z * r4.z + h4.w * r4.w;
                au += h4.x * u4.x + h4.y * u4.y + h4.z * u4.z + h4.w * u4.w;
                an += h4.x * n4.x + h4.y * n4.y + h4.z * n4.z + h4.w * n4.w;
            }
            const float* gi = gi0 + ((size_t)t * BB + b) * H3;
            float r = sigmoidf_(gi[j] + ar + bhh0[j]);
            float u = sigmoidf_(gi[HID + j] + au + bhh0[HID + j]);
            float n = tanhf(gi[2 * HID + j] + r * (an + bhh0[2 * HID + j]));
            h0seq[((size_t)t * BB + b) * HID + j] =
                (1.f - u) * n + u * sh[b * LDH + j];
        } else {
            const float4* xp = (const float4*)(sh + b * LDH);
            const float4* hp = (const float4*)(sh + 16 * LDH + b * LDH);
            const float4* ir = (const float4*)(wih1 + (size_t)j * HID);
            const float4* iu = (const float4*)(wih1 + (size_t)(HID + j) * HID);
            const float4* in_ = (const float4*)(wih1 + (size_t)(2 * HID + j) * HID);
            const float4* hr = (const float4*)(whh1 + (size_t)j * HID);
            const float4* hu = (const float4*)(whh1 + (size_t)(HID + j) * HID);
            const float4* hn = (const float4*)(whh1 + (size_t)(2 * HID + j) * HID);
            float air = 0.f, aiu = 0.f, ain = 0.f, ahr = 0.f, ahu = 0.f, ahn = 0.f;
#pragma unroll 4
            for (int k = 0; k < 256; k++) {
                float4 xv = xp[k], hv = hp[k];
                float4 a = ir[k], c = iu[k], e = in_[k];
                float4 f = hr[k], g = hu[k], q = hn[k];
                air += xv.x * a.x + xv.y * a.y + xv.z * a.z + xv.w * a.w;
                aiu += xv.x * c.x + xv.y * c.y + xv.z * c.z + xv.w * c.w;
                ain += xv.x * e.x + xv.y * e.y + xv.z * e.z + xv.w * e.w;
                ahr += hv.x * f.x + hv.y * f.y + hv.z * f.z + hv.w * f.w;
                ahu += hv.x * g.x + hv.y * g.y + hv.z * g.z + hv.w * g.w;
                ahn += hv.x * q.x + hv.y * q.y + hv.z * q.z + hv.w * q.w;
            }
            float r = sigmoidf_(air + bih1[j] + ahr + bhh1[j]);
            float u = sigmoidf_(aiu + bih1[HID + j] + ahu + bhh1[HID + j]);
            float n = tanhf(ain + bih1[2 * HID + j] + r * (ahn + bhh1[2 * HID + j]));
            h1seq[((size_t)b * TT + t) * HID + j] =
                (1.f - u) * n + u * sh[16 * LDH + b * LDH + j];
        }
        __threadfence();
        __syncthreads();
        if (tid == 0) atomicAdd(&cnt[(isA ? 0 : TT) + t], 1u);
    }
}

extern "C" void kernel_launch(void* const* d_in, const int* in_sizes, int n_in,
                              void* d_out, int out_size)
{
    const int*   seq  = (const int*)d_in[0];
    const float* emb  = (const float*)d_in[1];
    const float* wih0 = (const float*)d_in[2];
    const float* whh0 = (const float*)d_in[3];
    const float* bih0 = (const float*)d_in[4];
    const float* bhh0 = (const float*)d_in[5];
    const float* wih1 = (const float*)d_in[6];
    const float* whh1 = (const float*)d_in[7];
    const float* bih1 = (const float*)d_in[8];
    const float* bhh1 = (const float*)d_in[9];
    const float* wout = (const float*)d_in[10];
    const float* bout = (const float*)d_in[11];
    float* out = (float*)d_out;

    float *gi0, *h0seq, *h1seq; unsigned* cnt;
    cudaGetSymbolAddress((void**)&gi0,   g_gi0);
    cudaGetSymbolAddress((void**)&h0seq, g_h0seq);
    cudaGetSymbolAddress((void**)&h1seq, g_h1seq);
    cudaGetSymbolAddress((void**)&cnt,   g_cnt);

    zero_cnt_k<<<4, 256>>>(cnt);

    // gi0 = gather(emb) @ Wih0^T + b_ih0   (M=8192, N=3072, K=512)
    {
        dim3 g(H3 / 128, (BB * TT) / 128);
        gemm_tf32<1><<<g, 256>>>(emb, seq, wih0, bih0, gi0, BB * TT, H3, EMB, EMB);
    }

    const int smem = 2 * 16 * LDH * 4;  // 132 KB
    cudaFuncSetAttribute(gru_persistent, cudaFuncAttributeMaxDynamicSharedMemorySize, smem);
    gru_persistent<<<128, 256, smem>>>(gi0, whh0, bhh0, wih1, bih1, whh1, bhh1,
                                       h0seq, h1seq, cnt);

    tail_copy_k<<<(BB * HID + 255) / 256, 256>>>(h0seq, h1seq, out);

    // logits = h1seq @ Wout^T + b_out   (M=8192, N=32000, K=1024)
    {
        dim3 g(VOCAB / 128, (BB * TT) / 128);
        gemm_tf32<0><<<g, 256>>>(h1seq, nullptr, wout, bout, out, BB * TT, VOCAB, HID, HID);
    }
}

// round 5
// speedup vs baseline: 1.7567x; 1.7567x over previous
#include <cuda_runtime.h>
#include <mma.h>
#include <math.h>
#include <stdint.h>

using namespace nvcuda;

#define VOCAB 32000
#define EMB   512
#define HID   1024
#define BB    16
#define TT    512
#define H3    3072

// recurrence smem layout (floats)
#define LDH    1028
#define HBLK   (16 * LDH)          // 16448
#define RING_OFF (2 * HBLK)        // 32896
#define RPITCH 68
#define RSTAGE (96 * RPITCH)       // 6528
#define PART_OFF (RING_OFF + 2 * RSTAGE)  // 45952
#define REC_SMEM ((PART_OFF + 6 * 256) * 4)

__device__ float g_gi0[(size_t)TT * BB * H3];    // [t][b][3H]
__device__ float g_h0seq[(size_t)TT * BB * HID]; // [t][b][H]
__device__ float g_h1seq[(size_t)BB * TT * HID]; // [b][t][H]
__device__ unsigned g_cnt[2 * TT];

__device__ __forceinline__ float sigmoidf_(float x) { return 1.f / (1.f + expf(-x)); }
__device__ __forceinline__ void cpa16(uint32_t s, const void* g) {
    asm volatile("cp.async.cg.shared.global [%0], [%1], 16;\n" :: "r"(s), "l"(g));
}
__device__ __forceinline__ void cpa_commit() { asm volatile("cp.async.commit_group;\n"); }
template <int N> __device__ __forceinline__ void cpa_wait() {
    asm volatile("cp.async.wait_group %0;\n" :: "n"(N));
}

__global__ void zero_cnt_k(unsigned* c) {
    int i = blockIdx.x * blockDim.x + threadIdx.x;
    if (i < 2 * TT) c[i] = 0u;
}

__global__ void tail_copy_k(const float* __restrict__ h0seq,
                            const float* __restrict__ h1seq,
                            float* __restrict__ out) {
    int i = blockIdx.x * blockDim.x + threadIdx.x;
    if (i < BB * HID) {
        int b = i >> 10, j = i & 1023;
        out[(size_t)BB * TT * VOCAB + i] =
            h0seq[((size_t)(TT - 1) * BB + b) * HID + j];
        out[(size_t)BB * TT * VOCAB + BB * HID + i] =
            h1seq[((size_t)b * TT + (TT - 1)) * HID + j];
    }
}

// ---------------------------------------------------------------------------
// tf32 WMMA GEMM with 2-stage cp.async: C[M,N] = A[M,K] @ B[N,K]^T + bias[N]
// grid.x = M/128 (fastest -> A panel L2-resident), grid.y = N/128.
// ---------------------------------------------------------------------------
template <int GATHER>
__global__ void __launch_bounds__(256)
gemm_tf32(const float* __restrict__ A, const int* __restrict__ seq,
          const float* __restrict__ Bm, const float* __restrict__ bias,
          float* __restrict__ C, int M, int N, int K, int lda)
{
    extern __shared__ float sgm[];   // As[2][128*36] @0, Bs[2][128*36] @9216
    __shared__ float biasS[16][136];
    __shared__ int tokS[128];

    const int tid = threadIdx.x;
    const int m0 = blockIdx.x * 128;
    const int n0 = blockIdx.y * 128;

    if (GATHER && tid < 128) {
        int m = m0 + tid;
        tokS[tid] = seq[(m & 15) * TT + (m >> 4)];
    }
    for (int i = tid; i < 16 * 128; i += 256)
        biasS[i >> 7][i & 127] = bias[n0 + (i & 127)];
    __syncthreads();

    const uint32_t sb = (uint32_t)__cvta_generic_to_shared(sgm);
    const int KC = K >> 5;

    auto issue = [&](int kc, int st) {
        const int k0 = kc << 5;
#pragma unroll
        for (int rep = 0; rep < 4; rep++) {
            int i = tid + (rep << 8);           // 0..1023
            int row = i >> 3, c4 = i & 7;
            const float* srcA;
            if (GATHER) srcA = A + (size_t)tokS[row] * lda + k0 + c4 * 4;
            else        srcA = A + (size_t)(m0 + row) * lda + k0 + c4 * 4;
            cpa16(sb + 4u * (st * 4608 + row * 36 + c4 * 4), srcA);
            const float* srcB = Bm + (size_t)(n0 + row) * K + k0 + c4 * 4;
            cpa16(sb + 4u * (9216 + st * 4608 + row * 36 + c4 * 4), srcB);
        }
    };

    const int warpId = tid >> 5;
    const int wm = warpId >> 1;   // 0..3
    const int wn = warpId & 1;    // 0..1

    wmma::fragment<wmma::accumulator, 16, 16, 8, float> acc[2][4];
#pragma unroll
    for (int mi = 0; mi < 2; mi++)
#pragma unroll
        for (int ni = 0; ni < 4; ni++)
            wmma::load_matrix_sync(acc[mi][ni], &biasS[0][wn * 64 + ni * 16], 136,
                                   wmma::mem_row_major);

    issue(0, 0); cpa_commit();
    issue(1, 1); cpa_commit();

    for (int kc = 0; kc < KC; kc++) {
        cpa_wait<1>();
        __syncthreads();
        const int st = kc & 1;
        const float* As = sgm + st * 4608;
        const float* Bs = sgm + 9216 + st * 4608;
#pragma unroll
        for (int ks = 0; ks < 4; ks++) {
            wmma::fragment<wmma::matrix_a, 16, 16, 8, wmma::precision::tf32, wmma::row_major> a[2];
            wmma::fragment<wmma::matrix_b, 16, 16, 8, wmma::precision::tf32, wmma::col_major> b[4];
#pragma unroll
            for (int mi = 0; mi < 2; mi++) {
                wmma::load_matrix_sync(a[mi], As + (wm * 32 + mi * 16) * 36 + ks * 8, 36);
#pragma unroll
                for (int e = 0; e < a[mi].num_elements; e++)
                    a[mi].x[e] = wmma::__float_to_tf32(a[mi].x[e]);
            }
#pragma unroll
            for (int ni = 0; ni < 4; ni++) {
                wmma::load_matrix_sync(b[ni], Bs + (wn * 64 + ni * 16) * 36 + ks * 8, 36);
#pragma unroll
                for (int e = 0; e < b[ni].num_elements; e++)
                    b[ni].x[e] = wmma::__float_to_tf32(b[ni].x[e]);
            }
#pragma unroll
            for (int mi = 0; mi < 2; mi++)
#pragma unroll
                for (int ni = 0; ni < 4; ni++)
                    wmma::mma_sync(acc[mi][ni], a[mi], b[ni], acc[mi][ni]);
        }
        __syncthreads();
        if (kc + 2 < KC) issue(kc + 2, st);
        cpa_commit();
    }

#pragma unroll
    for (int mi = 0; mi < 2; mi++)
#pragma unroll
        for (int ni = 0; ni < 4; ni++)
            wmma::store_matrix_sync(C + (size_t)(m0 + wm * 32 + mi * 16) * N
                                      + n0 + wn * 64 + ni * 16,
                                    acc[mi][ni], N, wmma::mem_row_major);
}

// ---------------------------------------------------------------------------
// Persistent tensor-core GRU. 128 CTAs x 256 thr, 1 CTA/SM (~190KB smem).
// CTA<64: layer0 cols [cta*16,+16); CTA>=64: layer1.
// Warp g < ncw owns gate-dot over full K=1024 via tf32 wmma (m16n16k8);
// weights L2->smem 2-stage cp.async, chunk k=64. Counter chain in L2.
// ---------------------------------------------------------------------------
__global__ void __launch_bounds__(256, 1)
gru_persistent(const float* __restrict__ gi0,
               const float* __restrict__ whh0, const float* __restrict__ bhh0,
               const float* __restrict__ wih1, const float* __restrict__ bih1,
               const float* __restrict__ whh1, const float* __restrict__ bhh1,
               float* __restrict__ h0seq, float* __restrict__ h1seq,
               unsigned* __restrict__ cnt)
{
    extern __shared__ float sm[];
    const int tid = threadIdx.x;
    const int w = tid >> 5;
    const bool isA = blockIdx.x < 64;
    const int c0 = (isA ? blockIdx.x : blockIdx.x - 64) * 16;
    const int nrows = isA ? 48 : 96;
    const int ncw = isA ? 3 : 6;
    volatile unsigned* vc = cnt;
    const uint32_t sb = (uint32_t)__cvta_generic_to_shared(sm);

    auto issueW = [&](int ch, int st) {
        const int k0 = ch << 6;
#pragma unroll
        for (int rep = 0; rep < 6; rep++) {
            int i = tid + (rep << 8);
            if (i < nrows * 16) {
                int row = i >> 4, seg = i & 15;
                const float* W; int rr;
                if (isA) { W = whh0; rr = row; }
                else if (row < 48) { W = wih1; rr = row; }
                else { W = whh1; rr = row - 48; }
                int gate = rr >> 4, jl = rr & 15;
                const float* src = W + (size_t)(gate * HID + c0 + jl) * HID + k0 + seg * 4;
                cpa16(sb + 4u * (RING_OFF + st * RSTAGE + row * RPITCH + seg * 4), src);
            }
        }
    };

    wmma::fragment<wmma::accumulator, 16, 16, 8, float> acc;

    for (int t = 0; t < TT; t++) {
        // prefetch weight chunks 0,1 (independent of recurrence state)
        issueW(0, 0); cpa_commit();
        issueW(1, 1); cpa_commit();

        if (tid == 0) {
            if (isA) { if (t) while (vc[t - 1] < 64u) {} }
            else {
                while (vc[t] < 64u) {}
                if (t) while (vc[TT + t - 1] < 64u) {}
            }
        }
        __syncthreads();
        __threadfence();

        // stage A operands (fp32)
        if (isA) {
            if (t == 0) { for (int i = tid; i < HBLK; i += 256) sm[i] = 0.f; }
            else {
                const float* s = h0seq + (size_t)(t - 1) * BB * HID;
                for (int i = tid; i < 4096; i += 256) {
                    int b = i >> 8, k4 = i & 255;
                    *(float4*)&sm[b * LDH + k4 * 4] = *(const float4*)(s + b * HID + k4 * 4);
                }
            }
        } else {
            const float* sx = h0seq + (size_t)t * BB * HID;
            for (int i = tid; i < 4096; i += 256) {
                int b = i >> 8, k4 = i & 255;
                *(float4*)&sm[b * LDH + k4 * 4] = *(const float4*)(sx + b * HID + k4 * 4);
            }
            if (t == 0) { for (int i = tid; i < HBLK; i += 256) sm[HBLK + i] = 0.f; }
            else {
                for (int i = tid; i < 4096; i += 256) {
                    int b = i >> 8, k4 = i & 255;
                    *(float4*)&sm[HBLK + b * LDH + k4 * 4] =
                        *(const float4*)(h1seq + ((size_t)b * TT + (t - 1)) * HID + k4 * 4);
                }
            }
        }
        __syncthreads();

        wmma::fill_fragment(acc, 0.f);
        const float* Abase = (isA || w < 3) ? sm : (sm + HBLK);

        for (int ch = 0; ch < 16; ch++) {
            cpa_wait<1>();
            __syncthreads();
            const int st = ch & 1;
            if (w < ncw) {
                const float* Ap = Abase + (ch << 6);
                const float* Bp = sm + RING_OFF + st * RSTAGE + w * 16 * RPITCH;
#pragma unroll
                for (int ks = 0; ks < 8; ks++) {
                    wmma::fragment<wmma::matrix_a, 16, 16, 8, wmma::precision::tf32, wmma::row_major> af;
                    wmma::fragment<wmma::matrix_b, 16, 16, 8, wmma::precision::tf32, wmma::col_major> bf;
                    wmma::load_matrix_sync(af, Ap + ks * 8, LDH);
#pragma unroll
                    for (int e = 0; e < af.num_elements; e++)
                        af.x[e] = wmma::__float_to_tf32(af.x[e]);
                    wmma::load_matrix_sync(bf, Bp + ks * 8, RPITCH);
#pragma unroll
                    for (int e = 0; e < bf.num_elements; e++)
                        bf.x[e] = wmma::__float_to_tf32(bf.x[e]);
                    wmma::mma_sync(acc, af, bf, acc);
                }
            }
            __syncthreads();
            if (ch + 2 < 16) issueW(ch + 2, st);
            cpa_commit();
        }
        cpa_wait<0>();
        __syncthreads();

        if (w < ncw)
            wmma::store_matrix_sync(sm + PART_OFF + w * 256, acc, 16, wmma::mem_row_major);
        __syncthreads();

        {
            const int b = tid >> 4, jl = tid & 15;
            const int j = c0 + jl;
            const float* P = sm + PART_OFF;
            const int o = b * 16 + jl;
            if (isA) {
                const float* gi = gi0 + ((size_t)t * BB + b) * H3;
                float r = sigmoidf_(gi[j] + P[o] + bhh0[j]);
                float u = sigmoidf_(gi[HID + j] + P[256 + o] + bhh0[HID + j]);
                float n = tanhf(gi[2 * HID + j] + r * (P[512 + o] + bhh0[2 * HID + j]));
                float hprev = sm[b * LDH + j];
                h0seq[((size_t)t * BB + b) * HID + j] = (1.f - u) * n + u * hprev;
            } else {
                float r = sigmoidf_(P[o] + bih1[j] + P[768 + o] + bhh1[j]);
                float u = sigmoidf_(P[256 + o] + bih1[HID + j] + P[1024 + o] + bhh1[HID + j]);
                float n = tanhf(P[512 + o] + bih1[2 * HID + j]
                                + r * (P[1280 + o] + bhh1[2 * HID + j]));
                float hprev = sm[HBLK + b * LDH + j];
                h1seq[((size_t)b * TT + t) * HID + j] = (1.f - u) * n + u * hprev;
            }
        }
        __threadfence();
        __syncthreads();
        if (tid == 0) atomicAdd(&cnt[(isA ? 0 : TT) + t], 1u);
    }
}

extern "C" void kernel_launch(void* const* d_in, const int* in_sizes, int n_in,
                              void* d_out, int out_size)
{
    const int*   seq  = (const int*)d_in[0];
    const float* emb  = (const float*)d_in[1];
    const float* wih0 = (const float*)d_in[2];
    const float* whh0 = (const float*)d_in[3];
    const float* bih0 = (const float*)d_in[4];
    const float* bhh0 = (const float*)d_in[5];
    const float* wih1 = (const float*)d_in[6];
    const float* whh1 = (const float*)d_in[7];
    const float* bih1 = (const float*)d_in[8];
    const float* bhh1 = (const float*)d_in[9];
    const float* wout = (const float*)d_in[10];
    const float* bout = (const float*)d_in[11];
    float* out = (float*)d_out;

    float *gi0, *h0seq, *h1seq; unsigned* cnt;
    cudaGetSymbolAddress((void**)&gi0,   g_gi0);
    cudaGetSymbolAddress((void**)&h0seq, g_h0seq);
    cudaGetSymbolAddress((void**)&h1seq, g_h1seq);
    cudaGetSymbolAddress((void**)&cnt,   g_cnt);

    const int gemm_smem = 2 * 2 * 4608 * 4;  // 73728
    cudaFuncSetAttribute(gemm_tf32<1>, cudaFuncAttributeMaxDynamicSharedMemorySize, gemm_smem);
    cudaFuncSetAttribute(gemm_tf32<0>, cudaFuncAttributeMaxDynamicSharedMemorySize, gemm_smem);
    cudaFuncSetAttribute(gru_persistent, cudaFuncAttributeMaxDynamicSharedMemorySize, REC_SMEM);

    zero_cnt_k<<<4, 256>>>(cnt);

    // gi0 = gather(emb) @ Wih0^T + b_ih0   (M=8192, N=3072, K=512)
    {
        dim3 g(64, H3 / 128);
        gemm_tf32<1><<<g, 256, gemm_smem>>>(emb, seq, wih0, bih0, gi0, BB * TT, H3, EMB, EMB);
    }

    gru_persistent<<<128, 256, REC_SMEM>>>(gi0, whh0, bhh0, wih1, bih1, whh1, bhh1,
                                           h0seq, h1seq, cnt);

    tail_copy_k<<<(BB * HID + 255) / 256, 256>>>(h0seq, h1seq, out);

    // logits = h1seq @ Wout^T + b_out   (M=8192, N=32000, K=1024)
    {
        dim3 g(64, VOCAB / 128);
        gemm_tf32<0><<<g, 256, gemm_smem>>>(h1seq, nullptr, wout, bout, out, BB * TT, VOCAB, HID, HID);
    }
}

// round 6
// speedup vs baseline: 1.9452x; 1.1074x over previous
#include <cuda_runtime.h>
#include <mma.h>
#include <math.h>
#include <stdint.h>

using namespace nvcuda;

#define VOCAB 32000
#define EMB   512
#define HID   1024
#define BB    16
#define TT    512
#define H3    3072

// recurrence smem layout (floats)
#define LDH    1028
#define HBLK   (16 * LDH)                 // 16448
#define RING_OFF (2 * HBLK)               // 32896
#define RPITCH 68
#define RSTAGE (96 * RPITCH)              // 6528 floats (layer1 stage; layer0 uses less)
#define PART_OFF (RING_OFF + 3 * RSTAGE)  // 52480
#define GI_OFF   (PART_OFF + 6 * 256)     // 54016
#define REC_SMEM ((GI_OFF + 768) * 4)     // 219136 B

// packed weight blocks
#define CH0_FL (48 * RPITCH)              // 3264 floats / chunk (layer0)
#define CH1_FL (96 * RPITCH)              // 6528 floats / chunk (layer1)
#define CTA0_FL (16 * CH0_FL)             // per-CTA layer0
#define CTA1_FL (16 * CH1_FL)             // per-CTA layer1

__device__ float g_gi0[(size_t)TT * BB * H3];    // [t][cta][gate][b*16+jl] packed
__device__ float g_h0seq[(size_t)TT * BB * HID]; // [t][b][H]
__device__ float g_h1seq[(size_t)BB * TT * HID]; // [b][t][H]
__device__ float g_wpk0[(size_t)64 * CTA0_FL];
__device__ float g_wpk1[(size_t)64 * CTA1_FL];
__device__ unsigned g_cnt[2 * TT];

__device__ __forceinline__ float sigmoidf_(float x) { return 1.f / (1.f + expf(-x)); }
__device__ __forceinline__ void cpa16(uint32_t s, const void* g) {
    asm volatile("cp.async.cg.shared.global [%0], [%1], 16;\n" :: "r"(s), "l"(g));
}
__device__ __forceinline__ void cpa_commit() { asm volatile("cp.async.commit_group;\n"); }
template <int N> __device__ __forceinline__ void cpa_wait() {
    asm volatile("cp.async.wait_group %0;\n" :: "n"(N));
}
__device__ __forceinline__ void mbar_init(uint32_t mbar, unsigned cnt) {
    asm volatile("mbarrier.init.shared.b64 [%0], %1;" :: "r"(mbar), "r"(cnt) : "memory");
}
__device__ __forceinline__ void mbar_expect(uint32_t mbar, unsigned tx) {
    asm volatile("mbarrier.arrive.expect_tx.shared.b64 _, [%0], %1;"
                 :: "r"(mbar), "r"(tx) : "memory");
}
__device__ __forceinline__ void bulk_g2s(uint32_t sdst, const void* gsrc, unsigned bytes,
                                         uint32_t mbar) {
    asm volatile("cp.async.bulk.shared::cta.global.mbarrier::complete_tx::bytes "
                 "[%0], [%1], %2, [%3];"
                 :: "r"(sdst), "l"(gsrc), "r"(bytes), "r"(mbar) : "memory");
}
__device__ __forceinline__ void mbar_wait(uint32_t mbar, unsigned phase) {
    asm volatile(
        "{\n\t"
        ".reg .pred P1;\n\t"
        "LAB_W_%=:\n\t"
        "mbarrier.try_wait.parity.acquire.cta.shared::cta.b64 P1, [%0], %1;\n\t"
        "@P1 bra LAB_D_%=;\n\t"
        "bra LAB_W_%=;\n\t"
        "LAB_D_%=:\n\t"
        "}"
        :: "r"(mbar), "r"(phase) : "memory");
}

__global__ void zero_cnt_k(unsigned* c) {
    int i = blockIdx.x * blockDim.x + threadIdx.x;
    if (i < 2 * TT) c[i] = 0u;
}

// repack weights into per-CTA contiguous chunk blocks (pitch RPITCH, pad=0)
__global__ void repack_k(const float* __restrict__ whh0,
                         const float* __restrict__ wih1, const float* __restrict__ whh1,
                         float* __restrict__ wpk0, float* __restrict__ wpk1)
{
    const long tot0 = 64L * CTA0_FL, tot1 = 64L * CTA1_FL;
    long i = (long)blockIdx.x * blockDim.x + threadIdx.x;
    const long stride = (long)gridDim.x * blockDim.x;
    for (; i < tot0 + tot1; i += stride) {
        if (i < tot0) {
            long r = i; int k = r % RPITCH; r /= RPITCH;
            int row = r % 48; r /= 48;
            int ch = r % 16; int cta = r / 16;
            float v = 0.f;
            if (k < 64)
                v = whh0[((size_t)((row >> 4) * HID + cta * 16 + (row & 15))) * HID
                         + ch * 64 + k];
            wpk0[i] = v;
        } else {
            long r = i - tot0; int k = r % RPITCH; r /= RPITCH;
            int row = r % 96; r /= 96;
            int ch = r % 16; int cta = r / 16;
            float v = 0.f;
            if (k < 64) {
                const float* W = (row < 48) ? wih1 : whh1;
                int rr = (row < 48) ? row : row - 48;
                v = W[((size_t)((rr >> 4) * HID + cta * 16 + (rr & 15))) * HID
                      + ch * 64 + k];
            }
            wpk1[i - tot0] = v;
        }
    }
}

__global__ void tail_copy_k(const float* __restrict__ h0seq,
                            const float* __restrict__ h1seq,
                            float* __restrict__ out) {
    int i = blockIdx.x * blockDim.x + threadIdx.x;
    if (i < BB * HID) {
        int b = i >> 10, j = i & 1023;
        out[(size_t)BB * TT * VOCAB + i] =
            h0seq[((size_t)(TT - 1) * BB + b) * HID + j];
        out[(size_t)BB * TT * VOCAB + BB * HID + i] =
            h1seq[((size_t)b * TT + (TT - 1)) * HID + j];
    }
}

// ---------------------------------------------------------------------------
// tf32 WMMA GEMM, 2-stage cp.async. STORE_GI=1 -> store 16x16 tiles to the
// packed gi layout [t][colblk][gate][b*16+jl]; else normal row-major C.
// GATHER=1: A row m -> emb[seq[(m&15)*T + (m>>4)]].
// ---------------------------------------------------------------------------
template <int GATHER, int STORE_GI>
__global__ void __launch_bounds__(256)
gemm_tf32(const float* __restrict__ A, const int* __restrict__ seq,
          const float* __restrict__ Bm, const float* __restrict__ bias,
          float* __restrict__ C, int M, int N, int K, int lda)
{
    extern __shared__ float sgm[];   // As[2][128*36] @0, Bs[2][128*36] @9216
    __shared__ float biasS[16][136];
    __shared__ int tokS[128];

    const int tid = threadIdx.x;
    const int m0 = blockIdx.x * 128;
    const int n0 = blockIdx.y * 128;

    if (GATHER && tid < 128) {
        int m = m0 + tid;
        tokS[tid] = seq[(m & 15) * TT + (m >> 4)];
    }
    for (int i = tid; i < 16 * 128; i += 256)
        biasS[i >> 7][i & 127] = bias[n0 + (i & 127)];
    __syncthreads();

    const uint32_t sb = (uint32_t)__cvta_generic_to_shared(sgm);
    const int KC = K >> 5;

    auto issue = [&](int kc, int st) {
        const int k0 = kc << 5;
#pragma unroll
        for (int rep = 0; rep < 4; rep++) {
            int i = tid + (rep << 8);
            int row = i >> 3, c4 = i & 7;
            const float* srcA;
            if (GATHER) srcA = A + (size_t)tokS[row] * lda + k0 + c4 * 4;
            else        srcA = A + (size_t)(m0 + row) * lda + k0 + c4 * 4;
            cpa16(sb + 4u * (st * 4608 + row * 36 + c4 * 4), srcA);
            const float* srcB = Bm + (size_t)(n0 + row) * K + k0 + c4 * 4;
            cpa16(sb + 4u * (9216 + st * 4608 + row * 36 + c4 * 4), srcB);
        }
    };

    const int warpId = tid >> 5;
    const int wm = warpId >> 1;
    const int wn = warpId & 1;

    wmma::fragment<wmma::accumulator, 16, 16, 8, float> acc[2][4];
#pragma unroll
    for (int mi = 0; mi < 2; mi++)
#pragma unroll
        for (int ni = 0; ni < 4; ni++)
            wmma::load_matrix_sync(acc[mi][ni], &biasS[0][wn * 64 + ni * 16], 136,
                                   wmma::mem_row_major);

    issue(0, 0); cpa_commit();
    issue(1, 1); cpa_commit();

    for (int kc = 0; kc < KC; kc++) {
        cpa_wait<1>();
        __syncthreads();
        const int st = kc & 1;
        const float* As = sgm + st * 4608;
        const float* Bs = sgm + 9216 + st * 4608;
#pragma unroll
        for (int ks = 0; ks < 4; ks++) {
            wmma::fragment<wmma::matrix_a, 16, 16, 8, wmma::precision::tf32, wmma::row_major> a[2];
            wmma::fragment<wmma::matrix_b, 16, 16, 8, wmma::precision::tf32, wmma::col_major> b[4];
#pragma unroll
            for (int mi = 0; mi < 2; mi++) {
                wmma::load_matrix_sync(a[mi], As + (wm * 32 + mi * 16) * 36 + ks * 8, 36);
#pragma unroll
                for (int e = 0; e < a[mi].num_elements; e++)
                    a[mi].x[e] = wmma::__float_to_tf32(a[mi].x[e]);
            }
#pragma unroll
            for (int ni = 0; ni < 4; ni++) {
                wmma::load_matrix_sync(b[ni], Bs + (wn * 64 + ni * 16) * 36 + ks * 8, 36);
#pragma unroll
                for (int e = 0; e < b[ni].num_elements; e++)
                    b[ni].x[e] = wmma::__float_to_tf32(b[ni].x[e]);
            }
#pragma unroll
            for (int mi = 0; mi < 2; mi++)
#pragma unroll
                for (int ni = 0; ni < 4; ni++)
                    wmma::mma_sync(acc[mi][ni], a[mi], b[ni], acc[mi][ni]);
        }
        __syncthreads();
        if (kc + 2 < KC) issue(kc + 2, st);
        cpa_commit();
    }

#pragma unroll
    for (int mi = 0; mi < 2; mi++)
#pragma unroll
        for (int ni = 0; ni < 4; ni++) {
            int mrow = m0 + wm * 32 + mi * 16;
            int ncol = n0 + wn * 64 + ni * 16;
            if (STORE_GI) {
                int t = mrow >> 4;
                int gate = ncol >> 10;
                int colblk = (ncol & 1023) >> 4;
                wmma::store_matrix_sync(
                    C + (((size_t)t * 64 + colblk) * 3 + gate) * 256,
                    acc[mi][ni], 16, wmma::mem_row_major);
            } else {
                wmma::store_matrix_sync(C + (size_t)mrow * N + ncol,
                                        acc[mi][ni], N, wmma::mem_row_major);
            }
        }
}

// ---------------------------------------------------------------------------
// Persistent tensor-core GRU. 128 CTAs x 256 thr, 1 CTA/SM (~219KB smem).
// Weights streamed as prepacked contiguous chunks via cp.async.bulk +
// mbarrier (3-stage ring, continuous across steps). h/x/gi staged via bulk.
// ---------------------------------------------------------------------------
__global__ void __launch_bounds__(256, 1)
gru_persistent(const float* __restrict__ gi0,
               const float* __restrict__ wpk0, const float* __restrict__ bhh0,
               const float* __restrict__ wpk1, const float* __restrict__ bih1,
               const float* __restrict__ bhh1,
               float* __restrict__ h0seq, float* __restrict__ h1seq,
               unsigned* __restrict__ cnt)
{
    extern __shared__ float sm[];
    __shared__ __align__(8) unsigned long long mbars[4];  // 0..2 weights, 3 operands

    const int tid = threadIdx.x;
    const int w = tid >> 5;
    const bool isA = blockIdx.x < 64;
    const int cta = isA ? blockIdx.x : (blockIdx.x - 64);
    const int c0 = cta * 16;
    const int ncw = isA ? 3 : 6;
    volatile unsigned* vc = cnt;

    const float* wbase = isA ? (wpk0 + (size_t)cta * CTA0_FL)
                             : (wpk1 + (size_t)cta * CTA1_FL);
    const int chFl = isA ? CH0_FL : CH1_FL;
    const unsigned chBytes = (unsigned)(chFl * 4);

    const uint32_t smb = (uint32_t)__cvta_generic_to_shared(sm);
    const uint32_t mbb = (uint32_t)__cvta_generic_to_shared(mbars);

    if (tid == 0) {
        mbar_init(mbb + 0, 1);
        mbar_init(mbb + 8, 1);
        mbar_init(mbb + 16, 1);
        mbar_init(mbb + 24, 1);
        // prefetch weight chunks 0,1,2 into stages 0,1,2
#pragma unroll
        for (int s = 0; s < 3; s++) {
            mbar_expect(mbb + 8 * s, chBytes);
            bulk_g2s(smb + 4u * (RING_OFF + s * RSTAGE), wbase + s * chFl, chBytes,
                     mbb + 8 * s);
        }
    }
    __syncthreads();

    int ws = 0;           // weight ring cursor stage
    unsigned wpar = 0;    // its parity
    long gc = 0;          // global chunk counter
    const long GCMAX = (long)TT * 16;

    wmma::fragment<wmma::accumulator, 16, 16, 8, float> acc;

    for (int t = 0; t < TT; t++) {
        // ---- handoff spin ----
        if (tid == 0) {
            if (isA) { if (t) while (vc[t - 1] < 64u) {} }
            else {
                while (vc[t] < 64u) {}
                if (t) while (vc[TT + t - 1] < 64u) {}
            }
        }
        __syncthreads();
        __threadfence();

        // ---- stage operands via bulk copies ----
        if (isA) {
            if (tid == 0)
                mbar_expect(mbb + 24, 3072u + (t > 0 ? 65536u : 0u));
            __syncthreads();
            if (t == 0) {
                for (int i = tid; i < HBLK; i += 256) sm[i] = 0.f;
            }
            if (tid == 0)
                bulk_g2s(smb + 4u * GI_OFF,
                         gi0 + (((size_t)t * 64 + cta) * 3) * 256, 3072u, mbb + 24);
            if (t > 0 && tid < 16)
                bulk_g2s(smb + 4u * (tid * LDH),
                         h0seq + ((size_t)(t - 1) * BB + tid) * HID, 4096u, mbb + 24);
            mbar_wait(mbb + 24, (unsigned)(t & 1));
            __syncthreads();
        } else {
            if (tid == 0)
                mbar_expect(mbb + 24, t > 0 ? 131072u : 65536u);
            __syncthreads();
            if (t == 0) {
                for (int i = tid; i < HBLK; i += 256) sm[HBLK + i] = 0.f;
            }
            if (tid < 16)
                bulk_g2s(smb + 4u * (tid * LDH),
                         h0seq + ((size_t)t * BB + tid) * HID, 4096u, mbb + 24);
            if (t > 0 && tid >= 16 && tid < 32) {
                int b = tid - 16;
                bulk_g2s(smb + 4u * (HBLK + b * LDH),
                         h1seq + ((size_t)b * TT + (t - 1)) * HID, 4096u, mbb + 24);
            }
            mbar_wait(mbb + 24, (unsigned)(t & 1));
            __syncthreads();
        }

        // ---- K loop over 16 weight chunks ----
        wmma::fill_fragment(acc, 0.f);
        const float* Abase = (isA || w < 3) ? sm : (sm + HBLK);

        for (int ch = 0; ch < 16; ch++) {
            mbar_wait(mbb + 8 * ws, wpar);
            if (w < ncw) {
                const float* Ap = Abase + (ch << 6);
                const float* Bp = sm + RING_OFF + ws * RSTAGE + w * 16 * RPITCH;
#pragma unroll
                for (int ks = 0; ks < 8; ks++) {
                    wmma::fragment<wmma::matrix_a, 16, 16, 8, wmma::precision::tf32, wmma::row_major> af;
                    wmma::fragment<wmma::matrix_b, 16, 16, 8, wmma::precision::tf32, wmma::col_major> bf;
                    wmma::load_matrix_sync(af, Ap + ks * 8, LDH);
#pragma unroll
                    for (int e = 0; e < af.num_elements; e++)
                        af.x[e] = wmma::__float_to_tf32(af.x[e]);
                    wmma::load_matrix_sync(bf, Bp + ks * 8, RPITCH);
#pragma unroll
                    for (int e = 0; e < bf.num_elements; e++)
                        bf.x[e] = wmma::__float_to_tf32(bf.x[e]);
                    wmma::mma_sync(acc, af, bf, acc);
                }
            }
            __syncthreads();
            if (tid == 0 && gc + 3 < GCMAX) {
                int nch = (int)((gc + 3) & 15);
                mbar_expect(mbb + 8 * ws, chBytes);
                bulk_g2s(smb + 4u * (RING_OFF + ws * RSTAGE), wbase + nch * chFl,
                         chBytes, mbb + 8 * ws);
            }
            gc++;
            ws++;
            if (ws == 3) { ws = 0; wpar ^= 1u; }
        }

        // ---- epilogue ----
        if (w < ncw)
            wmma::store_matrix_sync(sm + PART_OFF + w * 256, acc, 16, wmma::mem_row_major);
        __syncthreads();

        {
            const int b = tid >> 4, jl = tid & 15;
            const int j = c0 + jl;
            const float* P = sm + PART_OFF;
            const int o = b * 16 + jl;
            if (isA) {
                const float* gis = sm + GI_OFF;
                float r = sigmoidf_(gis[o] + P[o] + bhh0[j]);
                float u = sigmoidf_(gis[256 + o] + P[256 + o] + bhh0[HID + j]);
                float n = tanhf(gis[512 + o] + r * (P[512 + o] + bhh0[2 * HID + j]));
                float hprev = sm[b * LDH + j];
                h0seq[((size_t)t * BB + b) * HID + j] = (1.f - u) * n + u * hprev;
            } else {
                float r = sigmoidf_(P[o] + bih1[j] + P[768 + o] + bhh1[j]);
                float u = sigmoidf_(P[256 + o] + bih1[HID + j] + P[1024 + o] + bhh1[HID + j]);
                float n = tanhf(P[512 + o] + bih1[2 * HID + j]
                                + r * (P[1280 + o] + bhh1[2 * HID + j]));
                float hprev = sm[HBLK + b * LDH + j];
                h1seq[((size_t)b * TT + t) * HID + j] = (1.f - u) * n + u * hprev;
            }
        }
        __threadfence();
        __syncthreads();
        if (tid == 0) atomicAdd(&cnt[(isA ? 0 : TT) + t], 1u);
    }
}

extern "C" void kernel_launch(void* const* d_in, const int* in_sizes, int n_in,
                              void* d_out, int out_size)
{
    const int*   seq  = (const int*)d_in[0];
    const float* emb  = (const float*)d_in[1];
    const float* wih0 = (const float*)d_in[2];
    const float* whh0 = (const float*)d_in[3];
    const float* bih0 = (const float*)d_in[4];
    const float* bhh0 = (const float*)d_in[5];
    const float* wih1 = (const float*)d_in[6];
    const float* whh1 = (const float*)d_in[7];
    const float* bih1 = (const float*)d_in[8];
    const float* bhh1 = (const float*)d_in[9];
    const float* wout = (const float*)d_in[10];
    const float* bout = (const float*)d_in[11];
    float* out = (float*)d_out;
    (void)bih0;

    float *gi0, *h0seq, *h1seq, *wpk0, *wpk1; unsigned* cnt;
    cudaGetSymbolAddress((void**)&gi0,   g_gi0);
    cudaGetSymbolAddress((void**)&h0seq, g_h0seq);
    cudaGetSymbolAddress((void**)&h1seq, g_h1seq);
    cudaGetSymbolAddress((void**)&wpk0,  g_wpk0);
    cudaGetSymbolAddress((void**)&wpk1,  g_wpk1);
    cudaGetSymbolAddress((void**)&cnt,   g_cnt);

    const int gemm_smem = 2 * 2 * 4608 * 4;  // 73728
    cudaFuncSetAttribute((const void*)gemm_tf32<1, 1>,
                         cudaFuncAttributeMaxDynamicSharedMemorySize, gemm_smem);
    cudaFuncSetAttribute((const void*)gemm_tf32<0, 0>,
                         cudaFuncAttributeMaxDynamicSharedMemorySize, gemm_smem);
    cudaFuncSetAttribute((const void*)gru_persistent,
                         cudaFuncAttributeMaxDynamicSharedMemorySize, REC_SMEM);

    zero_cnt_k<<<4, 256>>>(cnt);
    repack_k<<<4096, 256>>>(whh0, wih1, whh1, wpk0, wpk1);

    // gi0 packed = gather(emb) @ Wih0^T + b_ih0   (M=8192, N=3072, K=512)
    {
        dim3 g(64, H3 / 128);
        gemm_tf32<1, 1><<<g, 256, gemm_smem>>>(emb, seq, wih0, bih0, gi0,
                                               BB * TT, H3, EMB, EMB);
    }

    gru_persistent<<<128, 256, REC_SMEM>>>(gi0, wpk0, bhh0, wpk1, bih1, bhh1,
                                           h0seq, h1seq, cnt);

    tail_copy_k<<<(BB * HID + 255) / 256, 256>>>(h0seq, h1seq, out);

    // logits = h1seq @ Wout^T + b_out   (M=8192, N=32000, K=1024)
    {
        dim3 g(64, VOCAB / 128);
        gemm_tf32<0, 0><<<g, 256, gemm_smem>>>(h1seq, nullptr, wout, bout, out,
                                               BB * TT, VOCAB, HID, HID);
    }
}

// round 7
// speedup vs baseline: 1.9894x; 1.0227x over previous
#include <cuda_runtime.h>
#include <mma.h>
#include <math.h>
#include <stdint.h>

using namespace nvcuda;

#define VOCAB 32000
#define EMB   512
#define HID   1024
#define BB    16
#define TT    512
#define H3    3072

// recurrence smem layout (floats)
#define LDH    1028
#define HBLK   (16 * LDH)                 // 16448
#define RING_OFF (2 * HBLK)               // 32896
#define RPITCH 69                         // odd -> conflict-free B frag LDS
#define RSTAGE (96 * RPITCH)              // 6624
#define PART_OFF (RING_OFF + 3 * RSTAGE)  // 52768
#define GI_OFF   (PART_OFF + 6 * 256)     // 54304  (2 x 768 ping-pong)
#define REC_SMEM ((GI_OFF + 2 * 768) * 4) // 223360 B

// packed weight blocks
#define CH0_FL (48 * RPITCH)              // 3312 floats / chunk (layer0)
#define CH1_FL (96 * RPITCH)              // 6624 floats / chunk (layer1)
#define CTA0_FL (16 * CH0_FL)
#define CTA1_FL (16 * CH1_FL)

#define CSTRIDE 16                        // counter stride (one per 64B line)

__device__ float g_gi0[(size_t)TT * BB * H3];    // [t][cta][gate][b*16+jl] packed
__device__ float g_h0seq[(size_t)TT * BB * HID]; // [t][b][H]
__device__ float g_h1seq[(size_t)BB * TT * HID]; // [b][t][H] fp32 carry
__device__ float g_h1tf[(size_t)BB * TT * HID];  // tf32-rounded copy for GEMM
__device__ float g_wpk0[(size_t)64 * CTA0_FL];
__device__ float g_wpk1[(size_t)64 * CTA1_FL];
__device__ float g_wout_tf[(size_t)VOCAB * HID];
__device__ unsigned g_cnt[2 * TT * CSTRIDE];

__device__ __forceinline__ float sigmoidf_(float x) { return 1.f / (1.f + expf(-x)); }
__device__ __forceinline__ void cpa16(uint32_t s, const void* g) {
    asm volatile("cp.async.cg.shared.global [%0], [%1], 16;\n" :: "r"(s), "l"(g));
}
__device__ __forceinline__ void cpa_commit() { asm volatile("cp.async.commit_group;\n"); }
template <int N> __device__ __forceinline__ void cpa_wait() {
    asm volatile("cp.async.wait_group %0;\n" :: "n"(N));
}
__device__ __forceinline__ void mbar_init(uint32_t mbar, unsigned cnt) {
    asm volatile("mbarrier.init.shared.b64 [%0], %1;" :: "r"(mbar), "r"(cnt) : "memory");
}
__device__ __forceinline__ void mbar_expect(uint32_t mbar, unsigned tx) {
    asm volatile("mbarrier.arrive.expect_tx.shared.b64 _, [%0], %1;"
                 :: "r"(mbar), "r"(tx) : "memory");
}
__device__ __forceinline__ void bulk_g2s(uint32_t sdst, const void* gsrc, unsigned bytes,
                                         uint32_t mbar) {
    asm volatile("cp.async.bulk.shared::cta.global.mbarrier::complete_tx::bytes "
                 "[%0], [%1], %2, [%3];"
                 :: "r"(sdst), "l"(gsrc), "r"(bytes), "r"(mbar) : "memory");
}
__device__ __forceinline__ void mbar_wait(uint32_t mbar, unsigned phase) {
    asm volatile(
        "{\n\t"
        ".reg .pred P1;\n\t"
        "LAB_W_%=:\n\t"
        "mbarrier.try_wait.parity.acquire.cta.shared::cta.b64 P1, [%0], %1;\n\t"
        "@P1 bra LAB_D_%=;\n\t"
        "bra LAB_W_%=;\n\t"
        "LAB_D_%=:\n\t"
        "}"
        :: "r"(mbar), "r"(phase) : "memory");
}

__global__ void zero_cnt_k(unsigned* c) {
    int i = blockIdx.x * blockDim.x + threadIdx.x;
    if (i < 2 * TT * CSTRIDE) c[i] = 0u;
}

// tf32-pre-round w_out
__global__ void cvt_wout_k(const float4* __restrict__ src, float4* __restrict__ dst) {
    long n4 = (long)VOCAB * HID / 4;
    long i = (long)blockIdx.x * blockDim.x + threadIdx.x;
    long stride = (long)gridDim.x * blockDim.x;
    for (; i < n4; i += stride) {
        float4 v = src[i];
        v.x = wmma::__float_to_tf32(v.x); v.y = wmma::__float_to_tf32(v.y);
        v.z = wmma::__float_to_tf32(v.z); v.w = wmma::__float_to_tf32(v.w);
        dst[i] = v;
    }
}

// repack weights into per-CTA contiguous chunk blocks (pitch RPITCH, pad=0),
// pre-rounded to tf32.
__global__ void repack_k(const float* __restrict__ whh0,
                         const float* __restrict__ wih1, const float* __restrict__ whh1,
                         float* __restrict__ wpk0, float* __restrict__ wpk1)
{
    const long tot0 = 64L * CTA0_FL, tot1 = 64L * CTA1_FL;
    long i = (long)blockIdx.x * blockDim.x + threadIdx.x;
    const long stride = (long)gridDim.x * blockDim.x;
    for (; i < tot0 + tot1; i += stride) {
        if (i < tot0) {
            long r = i; int k = r % RPITCH; r /= RPITCH;
            int row = r % 48; r /= 48;
            int ch = r % 16; int cta = r / 16;
            float v = 0.f;
            if (k < 64)
                v = wmma::__float_to_tf32(
                    whh0[((size_t)((row >> 4) * HID + cta * 16 + (row & 15))) * HID
                         + ch * 64 + k]);
            wpk0[i] = v;
        } else {
            long r = i - tot0; int k = r % RPITCH; r /= RPITCH;
            int row = r % 96; r /= 96;
            int ch = r % 16; int cta = r / 16;
            float v = 0.f;
            if (k < 64) {
                const float* W = (row < 48) ? wih1 : whh1;
                int rr = (row < 48) ? row : row - 48;
                v = wmma::__float_to_tf32(
                    W[((size_t)((rr >> 4) * HID + cta * 16 + (rr & 15))) * HID
                      + ch * 64 + k]);
            }
            wpk1[i - tot0] = v;
        }
    }
}

__global__ void tail_copy_k(const float* __restrict__ h0seq,
                            const float* __restrict__ h1seq,
                            float* __restrict__ out) {
    int i = blockIdx.x * blockDim.x + threadIdx.x;
    if (i < BB * HID) {
        int b = i >> 10, j = i & 1023;
        out[(size_t)BB * TT * VOCAB + i] =
            h0seq[((size_t)(TT - 1) * BB + b) * HID + j];
        out[(size_t)BB * TT * VOCAB + BB * HID + i] =
            h1seq[((size_t)b * TT + (TT - 1)) * HID + j];
    }
}

// ---------------------------------------------------------------------------
// tf32 WMMA GEMM, 2-stage cp.async. STORE_GI=1 -> packed gi tile layout.
// NOCVT=1 -> inputs are pre-rounded tf32, skip convert loops.
// ---------------------------------------------------------------------------
template <int GATHER, int STORE_GI, int NOCVT>
__global__ void __launch_bounds__(256)
gemm_tf32(const float* __restrict__ A, const int* __restrict__ seq,
          const float* __restrict__ Bm, const float* __restrict__ bias,
          float* __restrict__ C, int M, int N, int K, int lda)
{
    extern __shared__ float sgm[];   // As[2][128*36] @0, Bs[2][128*36] @9216
    __shared__ float biasS[16][136];
    __shared__ int tokS[128];

    const int tid = threadIdx.x;
    const int m0 = blockIdx.x * 128;
    const int n0 = blockIdx.y * 128;

    if (GATHER && tid < 128) {
        int m = m0 + tid;
        tokS[tid] = seq[(m & 15) * TT + (m >> 4)];
    }
    for (int i = tid; i < 16 * 128; i += 256)
        biasS[i >> 7][i & 127] = bias[n0 + (i & 127)];
    __syncthreads();

    const uint32_t sb = (uint32_t)__cvta_generic_to_shared(sgm);
    const int KC = K >> 5;

    auto issue = [&](int kc, int st) {
        const int k0 = kc << 5;
#pragma unroll
        for (int rep = 0; rep < 4; rep++) {
            int i = tid + (rep << 8);
            int row = i >> 3, c4 = i & 7;
            const float* srcA;
            if (GATHER) srcA = A + (size_t)tokS[row] * lda + k0 + c4 * 4;
            else        srcA = A + (size_t)(m0 + row) * lda + k0 + c4 * 4;
            cpa16(sb + 4u * (st * 4608 + row * 36 + c4 * 4), srcA);
            const float* srcB = Bm + (size_t)(n0 + row) * K + k0 + c4 * 4;
            cpa16(sb + 4u * (9216 + st * 4608 + row * 36 + c4 * 4), srcB);
        }
    };

    const int warpId = tid >> 5;
    const int wm = warpId >> 1;
    const int wn = warpId & 1;

    wmma::fragment<wmma::accumulator, 16, 16, 8, float> acc[2][4];
#pragma unroll
    for (int mi = 0; mi < 2; mi++)
#pragma unroll
        for (int ni = 0; ni < 4; ni++)
            wmma::load_matrix_sync(acc[mi][ni], &biasS[0][wn * 64 + ni * 16], 136,
                                   wmma::mem_row_major);

    issue(0, 0); cpa_commit();
    issue(1, 1); cpa_commit();

    for (int kc = 0; kc < KC; kc++) {
        cpa_wait<1>();
        __syncthreads();
        const int st = kc & 1;
        const float* As = sgm + st * 4608;
        const float* Bs = sgm + 9216 + st * 4608;
#pragma unroll
        for (int ks = 0; ks < 4; ks++) {
            wmma::fragment<wmma::matrix_a, 16, 16, 8, wmma::precision::tf32, wmma::row_major> a[2];
            wmma::fragment<wmma::matrix_b, 16, 16, 8, wmma::precision::tf32, wmma::col_major> b[4];
#pragma unroll
            for (int mi = 0; mi < 2; mi++) {
                wmma::load_matrix_sync(a[mi], As + (wm * 32 + mi * 16) * 36 + ks * 8, 36);
                if (!NOCVT) {
#pragma unroll
                    for (int e = 0; e < a[mi].num_elements; e++)
                        a[mi].x[e] = wmma::__float_to_tf32(a[mi].x[e]);
                }
            }
#pragma unroll
            for (int ni = 0; ni < 4; ni++) {
                wmma::load_matrix_sync(b[ni], Bs + (wn * 64 + ni * 16) * 36 + ks * 8, 36);
                if (!NOCVT) {
#pragma unroll
                    for (int e = 0; e < b[ni].num_elements; e++)
                        b[ni].x[e] = wmma::__float_to_tf32(b[ni].x[e]);
                }
            }
#pragma unroll
            for (int mi = 0; mi < 2; mi++)
#pragma unroll
                for (int ni = 0; ni < 4; ni++)
                    wmma::mma_sync(acc[mi][ni], a[mi], b[ni], acc[mi][ni]);
        }
        __syncthreads();
        if (kc + 2 < KC) issue(kc + 2, st);
        cpa_commit();
    }

#pragma unroll
    for (int mi = 0; mi < 2; mi++)
#pragma unroll
        for (int ni = 0; ni < 4; ni++) {
            int mrow = m0 + wm * 32 + mi * 16;
            int ncol = n0 + wn * 64 + ni * 16;
            if (STORE_GI) {
                int t = mrow >> 4;
                int gate = ncol >> 10;
                int colblk = (ncol & 1023) >> 4;
                wmma::store_matrix_sync(
                    C + (((size_t)t * 64 + colblk) * 3 + gate) * 256,
                    acc[mi][ni], 16, wmma::mem_row_major);
            } else {
                wmma::store_matrix_sync(C + (size_t)mrow * N + ncol,
                                        acc[mi][ni], N, wmma::mem_row_major);
            }
        }
}

// ---------------------------------------------------------------------------
// Persistent tensor-core GRU. 128 CTAs x 256 thr, 1 CTA/SM (~223KB smem).
// Weights prepacked tf32 (no converts), cp.async.bulk 3-stage ring.
// gi slice double-buffered and prefetched one step ahead.
// ---------------------------------------------------------------------------
__global__ void __launch_bounds__(256, 1)
gru_persistent(const float* __restrict__ gi0,
               const float* __restrict__ wpk0, const float* __restrict__ bhh0,
               const float* __restrict__ wpk1, const float* __restrict__ bih1,
               const float* __restrict__ bhh1,
               float* __restrict__ h0seq, float* __restrict__ h1seq,
               float* __restrict__ h1tf,
               unsigned* __restrict__ cnt)
{
    extern __shared__ float sm[];
    __shared__ __align__(8) unsigned long long mbars[5];  // 0-2 weights, 3 operands, 4 gi

    const int tid = threadIdx.x;
    const int w = tid >> 5;
    const bool isA = blockIdx.x < 64;
    const int cta = isA ? blockIdx.x : (blockIdx.x - 64);
    const int c0 = cta * 16;
    const int ncw = isA ? 3 : 6;
    volatile unsigned* vc = cnt;

    const float* wbase = isA ? (wpk0 + (size_t)cta * CTA0_FL)
                             : (wpk1 + (size_t)cta * CTA1_FL);
    const int chFl = isA ? CH0_FL : CH1_FL;
    const unsigned chBytes = (unsigned)(chFl * 4);

    const uint32_t smb = (uint32_t)__cvta_generic_to_shared(sm);
    const uint32_t mbb = (uint32_t)__cvta_generic_to_shared(mbars);

    if (tid == 0) {
        for (int s = 0; s < 5; s++) mbar_init(mbb + 8 * s, 1);
#pragma unroll
        for (int s = 0; s < 3; s++) {
            mbar_expect(mbb + 8 * s, chBytes);
            bulk_g2s(smb + 4u * (RING_OFF + s * RSTAGE), wbase + s * chFl, chBytes,
                     mbb + 8 * s);
        }
        if (isA) {  // prefetch gi for t=0 into buffer 0
            mbar_expect(mbb + 32, 3072u);
            bulk_g2s(smb + 4u * GI_OFF, gi0 + ((size_t)0 * 64 + cta) * 3 * 256,
                     3072u, mbb + 32);
        }
    }
    __syncthreads();

    int ws = 0;
    unsigned wpar = 0;
    long gc = 0;
    const long GCMAX = (long)TT * 16;
    int hph = 0;   // operand barrier phase counter

    wmma::fragment<wmma::accumulator, 16, 16, 8, float> acc0, acc1;

    for (int t = 0; t < TT; t++) {
        // ---- handoff spin (strided counters + backoff) ----
        if (tid == 0) {
            unsigned sp;
            if (isA) {
                if (t) { sp = 0; while (vc[(t - 1) * CSTRIDE] < 64u) { if (++sp > 8) __nanosleep(64); } }
            } else {
                sp = 0; while (vc[t * CSTRIDE] < 64u) { if (++sp > 8) __nanosleep(64); }
                if (t) { sp = 0; while (vc[(TT + t - 1) * CSTRIDE] < 64u) { if (++sp > 8) __nanosleep(64); } }
            }
        }
        __syncthreads();
        __threadfence();

        // ---- stage h/x via bulk copies ----
        if (isA) {
            if (t == 0) {
                for (int i = tid; i < HBLK; i += 256) sm[i] = 0.f;
                __syncthreads();
            } else {
                if (tid == 0) mbar_expect(mbb + 24, 65536u);
                __syncthreads();
                if (tid < 16)
                    bulk_g2s(smb + 4u * (tid * LDH),
                             h0seq + ((size_t)(t - 1) * BB + tid) * HID, 4096u, mbb + 24);
                mbar_wait(mbb + 24, (unsigned)(hph & 1));
                hph++;
                __syncthreads();
            }
        } else {
            if (tid == 0) mbar_expect(mbb + 24, t > 0 ? 131072u : 65536u);
            __syncthreads();
            if (t == 0) {
                for (int i = tid; i < HBLK; i += 256) sm[HBLK + i] = 0.f;
            }
            if (tid < 16)
                bulk_g2s(smb + 4u * (tid * LDH),
                         h0seq + ((size_t)t * BB + tid) * HID, 4096u, mbb + 24);
            if (t > 0 && tid >= 16 && tid < 32) {
                int b = tid - 16;
                bulk_g2s(smb + 4u * (HBLK + b * LDH),
                         h1seq + ((size_t)b * TT + (t - 1)) * HID, 4096u, mbb + 24);
            }
            mbar_wait(mbb + 24, (unsigned)(hph & 1));
            hph++;
            __syncthreads();
        }

        // ---- K loop over 16 weight chunks (2 interleaved accumulators) ----
        wmma::fill_fragment(acc0, 0.f);
        wmma::fill_fragment(acc1, 0.f);
        const float* Abase = (isA || w < 3) ? sm : (sm + HBLK);

        for (int ch = 0; ch < 16; ch++) {
            mbar_wait(mbb + 8 * ws, wpar);
            if (w < ncw) {
                const float* Ap = Abase + (ch << 6);
                const float* Bp = sm + RING_OFF + ws * RSTAGE + w * 16 * RPITCH;
#pragma unroll
                for (int ks = 0; ks < 8; ks++) {
                    wmma::fragment<wmma::matrix_a, 16, 16, 8, wmma::precision::tf32, wmma::row_major> af;
                    wmma::fragment<wmma::matrix_b, 16, 16, 8, wmma::precision::tf32, wmma::col_major> bf;
                    wmma::load_matrix_sync(af, Ap + ks * 8, LDH);
#pragma unroll
                    for (int e = 0; e < af.num_elements; e++)
                        af.x[e] = wmma::__float_to_tf32(af.x[e]);
                    wmma::load_matrix_sync(bf, Bp + ks * 8, RPITCH);  // pre-rounded
                    if (ks & 1) wmma::mma_sync(acc1, af, bf, acc1);
                    else        wmma::mma_sync(acc0, af, bf, acc0);
                }
            }
            __syncthreads();
            if (tid == 0 && gc + 3 < GCMAX) {
                int nch = (int)((gc + 3) & 15);
                mbar_expect(mbb + 8 * ws, chBytes);
                bulk_g2s(smb + 4u * (RING_OFF + ws * RSTAGE), wbase + nch * chFl,
                         chBytes, mbb + 8 * ws);
            }
            gc++;
            ws++;
            if (ws == 3) { ws = 0; wpar ^= 1u; }
        }

        // ---- epilogue ----
        if (w < ncw) {
#pragma unroll
            for (int e = 0; e < acc0.num_elements; e++) acc0.x[e] += acc1.x[e];
            wmma::store_matrix_sync(sm + PART_OFF + w * 256, acc0, 16, wmma::mem_row_major);
        }
        __syncthreads();
        if (isA) mbar_wait(mbb + 32, (unsigned)(t & 1));   // gi[t] ready

        {
            const int b = tid >> 4, jl = tid & 15;
            const int j = c0 + jl;
            const float* P = sm + PART_OFF;
            const int o = b * 16 + jl;
            if (isA) {
                const float* gis = sm + GI_OFF + (t & 1) * 768;
                float r = sigmoidf_(gis[o] + P[o] + bhh0[j]);
                float u = sigmoidf_(gis[256 + o] + P[256 + o] + bhh0[HID + j]);
                float n = tanhf(gis[512 + o] + r * (P[512 + o] + bhh0[2 * HID + j]));
                float hprev = sm[b * LDH + j];
                h0seq[((size_t)t * BB + b) * HID + j] = (1.f - u) * n + u * hprev;
            } else {
                float r = sigmoidf_(P[o] + bih1[j] + P[768 + o] + bhh1[j]);
                float u = sigmoidf_(P[256 + o] + bih1[HID + j] + P[1024 + o] + bhh1[HID + j]);
                float n = tanhf(P[512 + o] + bih1[2 * HID + j]
                                + r * (P[1280 + o] + bhh1[2 * HID + j]));
                float hprev = sm[HBLK + b * LDH + j];
                float hnew = (1.f - u) * n + u * hprev;
                h1seq[((size_t)b * TT + t) * HID + j] = hnew;
                h1tf[((size_t)b * TT + t) * HID + j] = wmma::__float_to_tf32(hnew);
            }
        }
        __threadfence();
        __syncthreads();
        if (tid == 0) {
            atomicAdd(&cnt[((isA ? 0 : TT) + t) * CSTRIDE], 1u);
            if (isA && t + 1 < TT) {  // prefetch gi[t+1] into other buffer
                mbar_expect(mbb + 32, 3072u);
                bulk_g2s(smb + 4u * (GI_OFF + ((t + 1) & 1) * 768),
                         gi0 + ((size_t)(t + 1) * 64 + cta) * 3 * 256, 3072u, mbb + 32);
            }
        }
        __syncthreads();
    }
}

extern "C" void kernel_launch(void* const* d_in, const int* in_sizes, int n_in,
                              void* d_out, int out_size)
{
    const int*   seq  = (const int*)d_in[0];
    const float* emb  = (const float*)d_in[1];
    const float* wih0 = (const float*)d_in[2];
    const float* whh0 = (const float*)d_in[3];
    const float* bih0 = (const float*)d_in[4];
    const float* bhh0 = (const float*)d_in[5];
    const float* wih1 = (const float*)d_in[6];
    const float* whh1 = (const float*)d_in[7];
    const float* bih1 = (const float*)d_in[8];
    const float* bhh1 = (const float*)d_in[9];
    const float* wout = (const float*)d_in[10];
    const float* bout = (const float*)d_in[11];
    float* out = (float*)d_out;

    float *gi0, *h0seq, *h1seq, *h1tf, *wpk0, *wpk1, *wout_tf; unsigned* cnt;
    cudaGetSymbolAddress((void**)&gi0,     g_gi0);
    cudaGetSymbolAddress((void**)&h0seq,   g_h0seq);
    cudaGetSymbolAddress((void**)&h1seq,   g_h1seq);
    cudaGetSymbolAddress((void**)&h1tf,    g_h1tf);
    cudaGetSymbolAddress((void**)&wpk0,    g_wpk0);
    cudaGetSymbolAddress((void**)&wpk1,    g_wpk1);
    cudaGetSymbolAddress((void**)&wout_tf, g_wout_tf);
    cudaGetSymbolAddress((void**)&cnt,     g_cnt);

    const int gemm_smem = 2 * 2 * 4608 * 4;  // 73728
    cudaFuncSetAttribute((const void*)gemm_tf32<1, 1, 0>,
                         cudaFuncAttributeMaxDynamicSharedMemorySize, gemm_smem);
    cudaFuncSetAttribute((const void*)gemm_tf32<0, 0, 1>,
                         cudaFuncAttributeMaxDynamicSharedMemorySize, gemm_smem);
    cudaFuncSetAttribute((const void*)gru_persistent,
                         cudaFuncAttributeMaxDynamicSharedMemorySize, REC_SMEM);

    zero_cnt_k<<<64, 256>>>(cnt);
    repack_k<<<4096, 256>>>(whh0, wih1, whh1, wpk0, wpk1);
    cvt_wout_k<<<8192, 256>>>((const float4*)wout, (float4*)wout_tf);

    // gi0 packed = gather(emb) @ Wih0^T + b_ih0
    {
        dim3 g(64, H3 / 128);
        gemm_tf32<1, 1, 0><<<g, 256, gemm_smem>>>(emb, seq, wih0, bih0, gi0,
                                                  BB * TT, H3, EMB, EMB);
    }

    gru_persistent<<<128, 256, REC_SMEM>>>(gi0, wpk0, bhh0, wpk1, bih1, bhh1,
                                           h0seq, h1seq, h1tf, cnt);

    tail_copy_k<<<(BB * HID + 255) / 256, 256>>>(h0seq, h1seq, out);

    // logits = h1tf @ wout_tf^T + b_out  (pre-rounded tf32, no converts)
    {
        dim3 g(64, VOCAB / 128);
        gemm_tf32<0, 0, 1><<<g, 256, gemm_smem>>>(h1tf, nullptr, wout_tf, bout, out,
                                                  BB * TT, VOCAB, HID, HID);
    }
}

// round 8
// speedup vs baseline: 5.3357x; 2.6820x over previous
#include <cuda_runtime.h>
#include <cuda_fp16.h>
#include <mma.h>
#include <math.h>
#include <stdint.h>

using namespace nvcuda;

#define VOCAB 32000
#define EMB   512
#define HID   1024
#define BB    16
#define TT    512
#define H3    3072

// ---- recurrence smem layout (bytes) ----
#define LDHH   1040                     // halves pitch for A operands (2080 B/row)
#define A0_OFF 0                        // x / h0 operand  16 x LDHH halves
#define A1_OFF 33280                    // h1 operand (layer1)
#define RINGB  66560                    // weight ring, 3 stages
#define CH0H   (48 * 72)                // 3456 halves / chunk (layer0)
#define CH1H   (96 * 72)                // 6912 halves / chunk (layer1)
#define PARTB  108032                   // 6 x 256 fp32 partials
#define GIB    114176                   // 2 x 768 fp32 gi ping-pong
#define REC_SMEM 120320

#define CSTRIDE 16

__device__ float  g_gi0[(size_t)TT * BB * H3];      // packed [t][cta][gate][256]
__device__ __half g_h016[(size_t)TT * BB * HID];    // [t][b][H]
__device__ __half g_h116[(size_t)BB * TT * HID];    // [b][t][H] (= proj A)
__device__ float  g_h0fp[2 * 64 * 256];             // fp32 carry, ping-pong
__device__ float  g_h1fp[2 * 64 * 256];
__device__ __half g_wpk0[(size_t)64 * 16 * CH0H];
__device__ __half g_wpk1[(size_t)64 * 16 * CH1H];
__device__ __half g_emb16[(size_t)VOCAB * EMB];
__device__ __half g_wih016[(size_t)H3 * EMB];
__device__ __half g_wout16[(size_t)VOCAB * HID];
__device__ unsigned g_cnt[2 * TT * CSTRIDE];

__device__ __forceinline__ float sigmoidf_(float x) { return 1.f / (1.f + expf(-x)); }
__device__ __forceinline__ void mbar_init(uint32_t mbar, unsigned cnt) {
    asm volatile("mbarrier.init.shared.b64 [%0], %1;" :: "r"(mbar), "r"(cnt) : "memory");
}
__device__ __forceinline__ void mbar_expect(uint32_t mbar, unsigned tx) {
    asm volatile("mbarrier.arrive.expect_tx.shared.b64 _, [%0], %1;"
                 :: "r"(mbar), "r"(tx) : "memory");
}
__device__ __forceinline__ void bulk_g2s(uint32_t sdst, const void* gsrc, unsigned bytes,
                                         uint32_t mbar) {
    asm volatile("cp.async.bulk.shared::cta.global.mbarrier::complete_tx::bytes "
                 "[%0], [%1], %2, [%3];"
                 :: "r"(sdst), "l"(gsrc), "r"(bytes), "r"(mbar) : "memory");
}
__device__ __forceinline__ void mbar_wait(uint32_t mbar, unsigned phase) {
    asm volatile(
        "{\n\t"
        ".reg .pred P1;\n\t"
        "LAB_W_%=:\n\t"
        "mbarrier.try_wait.parity.acquire.cta.shared::cta.b64 P1, [%0], %1;\n\t"
        "@P1 bra LAB_D_%=;\n\t"
        "bra LAB_W_%=;\n\t"
        "LAB_D_%=:\n\t"
        "}"
        :: "r"(mbar), "r"(phase) : "memory");
}

__global__ void zero_cnt_k(unsigned* c) {
    int i = blockIdx.x * blockDim.x + threadIdx.x;
    if (i < 2 * TT * CSTRIDE) c[i] = 0u;
}

__global__ void f32_to_f16_k(const float4* __restrict__ src, __half2* __restrict__ dst,
                             long n4) {
    long i = (long)blockIdx.x * blockDim.x + threadIdx.x;
    long stride = (long)gridDim.x * blockDim.x;
    for (; i < n4; i += stride) {
        float4 v = src[i];
        dst[2 * i]     = __floats2half2_rn(v.x, v.y);
        dst[2 * i + 1] = __floats2half2_rn(v.z, v.w);
    }
}

// repack recurrence weights -> fp16 per-CTA contiguous chunks [cta][ch][row][72]
__global__ void repack_k(const float* __restrict__ whh0,
                         const float* __restrict__ wih1, const float* __restrict__ whh1,
                         __half* __restrict__ wpk0, __half* __restrict__ wpk1)
{
    const long tot0 = 64L * 16 * CH0H, tot1 = 64L * 16 * CH1H;
    long i = (long)blockIdx.x * blockDim.x + threadIdx.x;
    const long stride = (long)gridDim.x * blockDim.x;
    for (; i < tot0 + tot1; i += stride) {
        if (i < tot0) {
            long r = i; int k = (int)(r % 72); r /= 72;
            int row = (int)(r % 48); r /= 48;
            int ch = (int)(r % 16); int cta = (int)(r / 16);
            __half v = __float2half(0.f);
            if (k < 64)
                v = __float2half_rn(
                    whh0[((size_t)((row >> 4) * HID + cta * 16 + (row & 15))) * HID
                         + ch * 64 + k]);
            wpk0[i] = v;
        } else {
            long r = i - tot0; int k = (int)(r % 72); r /= 72;
            int row = (int)(r % 96); r /= 96;
            int ch = (int)(r % 16); int cta = (int)(r / 16);
            __half v = __float2half(0.f);
            if (k < 64) {
                const float* W = (row < 48) ? wih1 : whh1;
                int rr = (row < 48) ? row : row - 48;
                v = __float2half_rn(
                    W[((size_t)((rr >> 4) * HID + cta * 16 + (rr & 15))) * HID
                      + ch * 64 + k]);
            }
            wpk1[i - tot0] = v;
        }
    }
}

__global__ void tail_copy_k(const float* __restrict__ h0fp,
                            const float* __restrict__ h1fp,
                            float* __restrict__ out) {
    int i = blockIdx.x * blockDim.x + threadIdx.x;
    if (i < BB * HID) {
        int b = i >> 10, j = i & 1023;
        int cta = j >> 4, o = b * 16 + (j & 15);
        // t = 511 -> slot 1
        out[(size_t)BB * TT * VOCAB + i]            = h0fp[16384 + cta * 256 + o];
        out[(size_t)BB * TT * VOCAB + BB * HID + i] = h1fp[16384 + cta * 256 + o];
    }
}

// ---------------------------------------------------------------------------
// fp16 WMMA GEMM (fp32 accum): C[M,N] = A[M,K] @ B[N,K]^T + bias[N]
// Tiles 128x128, k-chunk 64, 2-stage ring fed by cp.async.bulk (1 bulk/row).
// 2 CTAs/SM. GATHER: A row m -> emb16[seq[(m&15)*T + (m>>4)]].
// STORE_GI: write packed gi tiles [t][colblk][gate][256].
// ---------------------------------------------------------------------------
template <int GATHER, int STORE_GI>
__global__ void __launch_bounds__(256, 2)
gemm_fp16(const __half* __restrict__ A, const int* __restrict__ seq,
          const __half* __restrict__ Bm, const float* __restrict__ bias,
          float* __restrict__ C, int M, int N, int K, int lda)
{
    extern __shared__ __half hsm[];        // 2 stages x (A 128x72 | B 128x72)
    __shared__ float biasS[16][136];
    __shared__ int tokS[128];
    __shared__ __align__(8) unsigned long long mb_[2];

    const int tid = threadIdx.x;
    const int m0 = blockIdx.x * 128;
    const int n0 = blockIdx.y * 128;

    if (GATHER && tid < 128) {
        int m = m0 + tid;
        tokS[tid] = seq[(m & 15) * TT + (m >> 4)];
    }
    for (int i = tid; i < 2048; i += 256)
        biasS[i >> 7][i & 127] = bias[n0 + (i & 127)];

    const uint32_t sb = (uint32_t)__cvta_generic_to_shared(hsm);
    const uint32_t mbb = (uint32_t)__cvta_generic_to_shared(mb_);
    const int KC = K >> 6;

    if (tid == 0) {
        mbar_init(mbb, 1); mbar_init(mbb + 8, 1);
        mbar_expect(mbb, 32768u); mbar_expect(mbb + 8, 32768u);
    }
    __syncthreads();   // tokS/biasS/mbar visible

    auto issue = [&](int kc, int st) {
        const int k0 = kc << 6;
        const int row = tid & 127;
        const uint32_t stb = sb + (uint32_t)st * 36864u;
        if (tid < 128) {
            const __half* src = GATHER ? (A + (size_t)tokS[row] * lda + k0)
                                       : (A + (size_t)(m0 + row) * lda + k0);
            bulk_g2s(stb + row * 144u, src, 128u, mbb + 8u * st);
        } else {
            bulk_g2s(stb + 18432u + row * 144u,
                     Bm + (size_t)(n0 + row) * K + k0, 128u, mbb + 8u * st);
        }
    };
    issue(0, 0);
    issue(1, 1);

    const int warpId = tid >> 5;
    const int wm = warpId >> 1;   // 0..3
    const int wn = warpId & 1;    // 0..1

    wmma::fragment<wmma::accumulator, 16, 16, 16, float> acc[2][4];
#pragma unroll
    for (int mi = 0; mi < 2; mi++)
#pragma unroll
        for (int ni = 0; ni < 4; ni++)
            wmma::load_matrix_sync(acc[mi][ni], &biasS[0][wn * 64 + ni * 16], 136,
                                   wmma::mem_row_major);

    for (int kc = 0; kc < KC; kc++) {
        const int st = kc & 1;
        mbar_wait(mbb + 8u * st, (unsigned)((kc >> 1) & 1));
        const __half* As = hsm + st * 18432;
        const __half* Bs = As + 9216;
#pragma unroll
        for (int ks = 0; ks < 4; ks++) {
            wmma::fragment<wmma::matrix_a, 16, 16, 16, __half, wmma::row_major> a[2];
            wmma::fragment<wmma::matrix_b, 16, 16, 16, __half, wmma::col_major> b[4];
#pragma unroll
            for (int mi = 0; mi < 2; mi++)
                wmma::load_matrix_sync(a[mi], As + (wm * 32 + mi * 16) * 72 + ks * 16, 72);
#pragma unroll
            for (int ni = 0; ni < 4; ni++)
                wmma::load_matrix_sync(b[ni], Bs + (wn * 64 + ni * 16) * 72 + ks * 16, 72);
#pragma unroll
            for (int mi = 0; mi < 2; mi++)
#pragma unroll
                for (int ni = 0; ni < 4; ni++)
                    wmma::mma_sync(acc[mi][ni], a[mi], b[ni], acc[mi][ni]);
        }
        __syncthreads();                 // stage st fully consumed
        if (kc + 2 < KC) {
            if (tid == 0) mbar_expect(mbb + 8u * st, 32768u);
            __syncthreads();             // expect before refills
            issue(kc + 2, st);
        }
    }

#pragma unroll
    for (int mi = 0; mi < 2; mi++)
#pragma unroll
        for (int ni = 0; ni < 4; ni++) {
            int mrow = m0 + wm * 32 + mi * 16;
            int ncol = n0 + wn * 64 + ni * 16;
            if (STORE_GI) {
                int t = mrow >> 4;
                int gate = ncol >> 10;
                int colblk = (ncol & 1023) >> 4;
                wmma::store_matrix_sync(
                    C + (((size_t)t * 64 + colblk) * 3 + gate) * 256,
                    acc[mi][ni], 16, wmma::mem_row_major);
            } else {
                wmma::store_matrix_sync(C + (size_t)mrow * N + ncol,
                                        acc[mi][ni], N, wmma::mem_row_major);
            }
        }
}

// ---------------------------------------------------------------------------
// Persistent fp16 tensor-core GRU. 128 CTAs x 256 thr.
// fp16 weights/operands for MMA; fp32 carry via small packed side arrays.
// ---------------------------------------------------------------------------
__global__ void __launch_bounds__(256, 1)
gru_persistent(const float* __restrict__ gi0,
               const __half* __restrict__ wpk0, const float* __restrict__ bhh0,
               const __half* __restrict__ wpk1, const float* __restrict__ bih1,
               const float* __restrict__ bhh1,
               __half* __restrict__ h016, __half* __restrict__ h116,
               float* __restrict__ h0fp, float* __restrict__ h1fp,
               unsigned* __restrict__ cnt)
{
    extern __shared__ char smraw[];
    __half* smA0 = (__half*)smraw;
    __half* smA1 = (__half*)(smraw + A1_OFF);
    __half* ring = (__half*)(smraw + RINGB);
    float*  P    = (float*)(smraw + PARTB);
    float*  GIS  = (float*)(smraw + GIB);
    __shared__ __align__(8) unsigned long long mbars[5];  // 0-2 wring, 3 oper, 4 gi

    const int tid = threadIdx.x;
    const int w = tid >> 5;
    const bool isA = blockIdx.x < 64;
    const int cta = isA ? blockIdx.x : (blockIdx.x - 64);
    const int c0 = cta * 16;
    const int ncw = isA ? 3 : 6;
    const int bb = tid >> 4, jl = tid & 15;
    const int j = c0 + jl;
    volatile unsigned* vc = cnt;

    const __half* wbase = isA ? (wpk0 + (size_t)cta * 16 * CH0H)
                              : (wpk1 + (size_t)cta * 16 * CH1H);
    const int chH = isA ? CH0H : CH1H;
    const unsigned chBytes = (unsigned)(chH * 2);

    const uint32_t smb = (uint32_t)__cvta_generic_to_shared(smraw);
    const uint32_t mbb = (uint32_t)__cvta_generic_to_shared(mbars);

    // biases cached in registers (invariant over t)
    float B0r = 0.f, B0u = 0.f, B0n = 0.f;
    float B1ir = 0.f, B1iu = 0.f, B1in = 0.f, B1hr = 0.f, B1hu = 0.f, B1hn = 0.f;
    if (isA) {
        B0r = bhh0[j]; B0u = bhh0[HID + j]; B0n = bhh0[2 * HID + j];
    } else {
        B1ir = bih1[j]; B1iu = bih1[HID + j]; B1in = bih1[2 * HID + j];
        B1hr = bhh1[j]; B1hu = bhh1[HID + j]; B1hn = bhh1[2 * HID + j];
    }

    if (tid == 0) {
        for (int s = 0; s < 5; s++) mbar_init(mbb + 8 * s, 1);
#pragma unroll
        for (int s = 0; s < 3; s++) {
            mbar_expect(mbb + 8 * s, chBytes);
            bulk_g2s(smb + RINGB + (uint32_t)s * chBytes, wbase + (size_t)s * chH,
                     chBytes, mbb + 8 * s);
        }
        if (isA) {
            mbar_expect(mbb + 32, 3072u);
            bulk_g2s(smb + GIB, gi0 + (size_t)cta * 3 * 256, 3072u, mbb + 32);
        }
    }
    __syncthreads();

    int ws = 0;
    unsigned wpar = 0;
    long gc = 0;
    const long GCMAX = (long)TT * 16;
    int hph = 0;

    wmma::fragment<wmma::accumulator, 16, 16, 16, float> acc0, acc1;

    for (int t = 0; t < TT; t++) {
        // ---- handoff spin ----
        if (tid == 0) {
            unsigned sp;
            if (isA) {
                if (t) { sp = 0; while (vc[(t - 1) * CSTRIDE] < 64u) { if (++sp > 16) __nanosleep(32); } }
            } else {
                sp = 0; while (vc[t * CSTRIDE] < 64u) { if (++sp > 16) __nanosleep(32); }
                if (t) { sp = 0; while (vc[(TT + t - 1) * CSTRIDE] < 64u) { if (++sp > 16) __nanosleep(32); } }
            }
        }
        __syncthreads();
        __threadfence();

        // ---- stage fp16 A operands ----
        if (isA) {
            if (t == 0) {
                for (int i = tid; i < 8320; i += 256) ((uint32_t*)smA0)[i] = 0u;
                __syncthreads();
            } else {
                if (tid == 0) mbar_expect(mbb + 24, 32768u);
                __syncthreads();
                if (tid < 16)
                    bulk_g2s(smb + A0_OFF + tid * 2080u,
                             h016 + ((size_t)(t - 1) * BB + tid) * HID, 2048u, mbb + 24);
                mbar_wait(mbb + 24, (unsigned)(hph & 1));
                hph++;
                __syncthreads();
            }
        } else {
            if (tid == 0) mbar_expect(mbb + 24, t > 0 ? 65536u : 32768u);
            __syncthreads();
            if (t == 0) {
                for (int i = tid; i < 8320; i += 256) ((uint32_t*)smA1)[i] = 0u;
            }
            if (tid < 16)
                bulk_g2s(smb + A0_OFF + tid * 2080u,
                         h016 + ((size_t)t * BB + tid) * HID, 2048u, mbb + 24);
            if (t > 0 && tid >= 16 && tid < 32) {
                int b = tid - 16;
                bulk_g2s(smb + A1_OFF + b * 2080u,
                         h116 + ((size_t)b * TT + (t - 1)) * HID, 2048u, mbb + 24);
            }
            mbar_wait(mbb + 24, (unsigned)(hph & 1));
            hph++;
            __syncthreads();
        }

        // fp32 carry prefetch (ready by epilogue)
        float hprev = 0.f;
        if (t > 0)
            hprev = (isA ? h0fp : h1fp)[((t + 1) & 1) * 16384 + cta * 256 + tid];

        // ---- K loop over 16 fp16 weight chunks ----
        wmma::fill_fragment(acc0, 0.f);
        wmma::fill_fragment(acc1, 0.f);
        const __half* Ab = (isA || w < 3) ? smA0 : smA1;

        for (int ch = 0; ch < 16; ch++) {
            mbar_wait(mbb + 8 * ws, wpar);
            if (w < ncw) {
                const __half* Ap = Ab + (ch << 6);
                const __half* Bp = ring + ws * chH + w * 16 * 72;
#pragma unroll
                for (int ks = 0; ks < 4; ks++) {
                    wmma::fragment<wmma::matrix_a, 16, 16, 16, __half, wmma::row_major> af;
                    wmma::fragment<wmma::matrix_b, 16, 16, 16, __half, wmma::col_major> bf;
                    wmma::load_matrix_sync(af, Ap + ks * 16, LDHH);
                    wmma::load_matrix_sync(bf, Bp + ks * 16, 72);
                    if (ks & 1) wmma::mma_sync(acc1, af, bf, acc1);
                    else        wmma::mma_sync(acc0, af, bf, acc0);
                }
            }
            __syncthreads();
            if (tid == 0 && gc + 3 < GCMAX) {
                int nch = (int)((gc + 3) & 15);
                mbar_expect(mbb + 8 * ws, chBytes);
                bulk_g2s(smb + RINGB + (uint32_t)ws * chBytes,
                         wbase + (size_t)nch * chH, chBytes, mbb + 8 * ws);
            }
            gc++;
            ws++;
            if (ws == 3) { ws = 0; wpar ^= 1u; }
        }

        // ---- epilogue ----
        if (w < ncw) {
#pragma unroll
            for (int e = 0; e < acc0.num_elements; e++) acc0.x[e] += acc1.x[e];
            wmma::store_matrix_sync(P + w * 256, acc0, 16, wmma::mem_row_major);
        }
        __syncthreads();
        if (isA) mbar_wait(mbb + 32, (unsigned)(t & 1));

        {
            const int o = tid;   // bb*16 + jl
            if (isA) {
                const float* gis = GIS + (t & 1) * 768;
                float r = sigmoidf_(gis[o] + P[o] + B0r);
                float u = sigmoidf_(gis[256 + o] + P[256 + o] + B0u);
                float n = tanhf(gis[512 + o] + r * (P[512 + o] + B0n));
                float hnew = (1.f - u) * n + u * hprev;
                h016[((size_t)t * BB + bb) * HID + j] = __float2half_rn(hnew);
                h0fp[(t & 1) * 16384 + cta * 256 + o] = hnew;
            } else {
                float r = sigmoidf_(P[o] + B1ir + P[768 + o] + B1hr);
                float u = sigmoidf_(P[256 + o] + B1iu + P[1024 + o] + B1hu);
                float n = tanhf(P[512 + o] + B1in + r * (P[1280 + o] + B1hn));
                float hnew = (1.f - u) * n + u * hprev;
                h116[((size_t)bb * TT + t) * HID + j] = __float2half_rn(hnew);
                h1fp[(t & 1) * 16384 + cta * 256 + o] = hnew;
            }
        }
        __threadfence();
        __syncthreads();
        if (tid == 0) {
            atomicAdd(&cnt[((isA ? 0 : TT) + t) * CSTRIDE], 1u);
            if (isA && t + 1 < TT) {
                mbar_expect(mbb + 32, 3072u);
                bulk_g2s(smb + GIB + (uint32_t)(((t + 1) & 1) * 3072),
                         gi0 + ((size_t)(t + 1) * 64 + cta) * 3 * 256, 3072u, mbb + 32);
            }
        }
        __syncthreads();
    }
}

extern "C" void kernel_launch(void* const* d_in, const int* in_sizes, int n_in,
                              void* d_out, int out_size)
{
    const int*   seq  = (const int*)d_in[0];
    const float* emb  = (const float*)d_in[1];
    const float* wih0 = (const float*)d_in[2];
    const float* whh0 = (const float*)d_in[3];
    const float* bih0 = (const float*)d_in[4];
    const float* bhh0 = (const float*)d_in[5];
    const float* wih1 = (const float*)d_in[6];
    const float* whh1 = (const float*)d_in[7];
    const float* bih1 = (const float*)d_in[8];
    const float* bhh1 = (const float*)d_in[9];
    const float* wout = (const float*)d_in[10];
    const float* bout = (const float*)d_in[11];
    float* out = (float*)d_out;

    float *gi0, *h0fp, *h1fp; __half *h016, *h116, *wpk0, *wpk1, *emb16, *wih016, *wout16;
    unsigned* cnt;
    cudaGetSymbolAddress((void**)&gi0,    g_gi0);
    cudaGetSymbolAddress((void**)&h016,   g_h016);
    cudaGetSymbolAddress((void**)&h116,   g_h116);
    cudaGetSymbolAddress((void**)&h0fp,   g_h0fp);
    cudaGetSymbolAddress((void**)&h1fp,   g_h1fp);
    cudaGetSymbolAddress((void**)&wpk0,   g_wpk0);
    cudaGetSymbolAddress((void**)&wpk1,   g_wpk1);
    cudaGetSymbolAddress((void**)&emb16,  g_emb16);
    cudaGetSymbolAddress((void**)&wih016, g_wih016);
    cudaGetSymbolAddress((void**)&wout16, g_wout16);
    cudaGetSymbolAddress((void**)&cnt,    g_cnt);

    const int gemm_smem = 73728;
    cudaFuncSetAttribute((const void*)gemm_fp16<1, 1>,
                         cudaFuncAttributeMaxDynamicSharedMemorySize, gemm_smem);
    cudaFuncSetAttribute((const void*)gemm_fp16<0, 0>,
                         cudaFuncAttributeMaxDynamicSharedMemorySize, gemm_smem);
    cudaFuncSetAttribute((const void*)gru_persistent,
                         cudaFuncAttributeMaxDynamicSharedMemorySize, REC_SMEM);

    zero_cnt_k<<<64, 256>>>(cnt);
    f32_to_f16_k<<<4096, 256>>>((const float4*)emb,  (__half2*)emb16,  (long)VOCAB * EMB / 4);
    f32_to_f16_k<<<2048, 256>>>((const float4*)wih0, (__half2*)wih016, (long)H3 * EMB / 4);
    f32_to_f16_k<<<4096, 256>>>((const float4*)wout, (__half2*)wout16, (long)VOCAB * HID / 4);
    repack_k<<<4096, 256>>>(whh0, wih1, whh1, wpk0, wpk1);

    // gi0 packed = gather(emb16) @ wih016^T + b_ih0   (M=8192, N=3072, K=512)
    {
        dim3 g(64, H3 / 128);
        gemm_fp16<1, 1><<<g, 256, gemm_smem>>>(emb16, seq, wih016, bih0, gi0,
                                               BB * TT, H3, EMB, EMB);
    }

    gru_persistent<<<128, 256, REC_SMEM>>>(gi0, wpk0, bhh0, wpk1, bih1, bhh1,
                                           h016, h116, h0fp, h1fp, cnt);

    tail_copy_k<<<(BB * HID + 255) / 256, 256>>>(h0fp, h1fp, out);

    // logits = h116 @ wout16^T + b_out   (M=8192 [b][t], N=32000, K=1024)
    {
        dim3 g(64, VOCAB / 128);
        gemm_fp16<0, 0><<<g, 256, gemm_smem>>>(h116, nullptr, wout16, bout, out,
                                               BB * TT, VOCAB, HID, HID);
    }
}

// round 9
// speedup vs baseline: 5.7943x; 1.0859x over previous
#include <cuda_runtime.h>
#include <cuda_fp16.h>
#include <mma.h>
#include <math.h>
#include <stdint.h>

using namespace nvcuda;

#define VOCAB 32000
#define EMB   512
#define HID   1024
#define BB    16
#define TT    512
#define H3    3072

// ---- recurrence smem layout (bytes) ----
#define LDHH   1040                     // halves pitch for A operands (2080 B/row)
#define A0_OFF 0                        // x / h0 operand  16 x LDHH halves
#define A1_OFF 33280                    // h1 operand (layer1)
#define RINGB  66560                    // weight ring, 3 stages (layer1 stage 26112 B)
#define NCHK   8                        // k-chunks per step (k=128 each)
#define WPITCH 136                      // halves per packed weight row (128 + 8 pad)
#define CH0H   (48 * WPITCH)            // 6528 halves / chunk (layer0)
#define CH1H   (96 * WPITCH)            // 13056 halves / chunk (layer1)
#define PARTB  144896                   // 6 x 256 fp32 partials
#define GIB    151040                   // 2 x 768 fp32 gi ping-pong
#define REC_SMEM 157184

#define CSTRIDE 16

__device__ float  g_gi0[(size_t)TT * BB * H3];      // packed [t][cta][gate][256]
__device__ __half g_h016[(size_t)TT * BB * HID];    // [t][b][H]
__device__ __half g_h116[(size_t)BB * TT * HID];    // [b][t][H] (= proj A)
__device__ float  g_h0fp[2 * 64 * 256];             // fp32 carry, ping-pong
__device__ float  g_h1fp[2 * 64 * 256];
__device__ __half g_wpk0[(size_t)64 * NCHK * CH0H];
__device__ __half g_wpk1[(size_t)64 * NCHK * CH1H];
__device__ __half g_emb16[(size_t)VOCAB * EMB];
__device__ __half g_wih016[(size_t)H3 * EMB];
__device__ __half g_wout16[(size_t)VOCAB * HID];
__device__ unsigned g_cnt[2 * TT * CSTRIDE];

__device__ __forceinline__ float sigmoidf_(float x) { return 1.f / (1.f + expf(-x)); }
__device__ __forceinline__ void mbar_init(uint32_t mbar, unsigned cnt) {
    asm volatile("mbarrier.init.shared.b64 [%0], %1;" :: "r"(mbar), "r"(cnt) : "memory");
}
__device__ __forceinline__ void mbar_expect(uint32_t mbar, unsigned tx) {
    asm volatile("mbarrier.arrive.expect_tx.shared.b64 _, [%0], %1;"
                 :: "r"(mbar), "r"(tx) : "memory");
}
__device__ __forceinline__ void bulk_g2s(uint32_t sdst, const void* gsrc, unsigned bytes,
                                         uint32_t mbar) {
    asm volatile("cp.async.bulk.shared::cta.global.mbarrier::complete_tx::bytes "
                 "[%0], [%1], %2, [%3];"
                 :: "r"(sdst), "l"(gsrc), "r"(bytes), "r"(mbar) : "memory");
}
__device__ __forceinline__ void mbar_wait(uint32_t mbar, unsigned phase) {
    asm volatile(
        "{\n\t"
        ".reg .pred P1;\n\t"
        "LAB_W_%=:\n\t"
        "mbarrier.try_wait.parity.acquire.cta.shared::cta.b64 P1, [%0], %1;\n\t"
        "@P1 bra LAB_D_%=;\n\t"
        "bra LAB_W_%=;\n\t"
        "LAB_D_%=:\n\t"
        "}"
        :: "r"(mbar), "r"(phase) : "memory");
}

__global__ void zero_cnt_k(unsigned* c) {
    int i = blockIdx.x * blockDim.x + threadIdx.x;
    if (i < 2 * TT * CSTRIDE) c[i] = 0u;
}

__global__ void f32_to_f16_k(const float4* __restrict__ src, __half2* __restrict__ dst,
                             long n4) {
    long i = (long)blockIdx.x * blockDim.x + threadIdx.x;
    long stride = (long)gridDim.x * blockDim.x;
    for (; i < n4; i += stride) {
        float4 v = src[i];
        dst[2 * i]     = __floats2half2_rn(v.x, v.y);
        dst[2 * i + 1] = __floats2half2_rn(v.z, v.w);
    }
}

// repack recurrence weights -> fp16 per-CTA contiguous chunks [cta][ch][row][WPITCH]
__global__ void repack_k(const float* __restrict__ whh0,
                         const float* __restrict__ wih1, const float* __restrict__ whh1,
                         __half* __restrict__ wpk0, __half* __restrict__ wpk1)
{
    const long tot0 = 64L * NCHK * CH0H, tot1 = 64L * NCHK * CH1H;
    long i = (long)blockIdx.x * blockDim.x + threadIdx.x;
    const long stride = (long)gridDim.x * blockDim.x;
    for (; i < tot0 + tot1; i += stride) {
        if (i < tot0) {
            long r = i; int k = (int)(r % WPITCH); r /= WPITCH;
            int row = (int)(r % 48); r /= 48;
            int ch = (int)(r % NCHK); int cta = (int)(r / NCHK);
            __half v = __float2half(0.f);
            if (k < 128)
                v = __float2half_rn(
                    whh0[((size_t)((row >> 4) * HID + cta * 16 + (row & 15))) * HID
                         + ch * 128 + k]);
            wpk0[i] = v;
        } else {
            long r = i - tot0; int k = (int)(r % WPITCH); r /= WPITCH;
            int row = (int)(r % 96); r /= 96;
            int ch = (int)(r % NCHK); int cta = (int)(r / NCHK);
            __half v = __float2half(0.f);
            if (k < 128) {
                const float* W = (row < 48) ? wih1 : whh1;
                int rr = (row < 48) ? row : row - 48;
                v = __float2half_rn(
                    W[((size_t)((rr >> 4) * HID + cta * 16 + (rr & 15))) * HID
                      + ch * 128 + k]);
            }
            wpk1[i - tot0] = v;
        }
    }
}

__global__ void tail_copy_k(const float* __restrict__ h0fp,
                            const float* __restrict__ h1fp,
                            float* __restrict__ out) {
    int i = blockIdx.x * blockDim.x + threadIdx.x;
    if (i < BB * HID) {
        int b = i >> 10, j = i & 1023;
        int cta = j >> 4, o = b * 16 + (j & 15);
        // t = 511 -> slot 1
        out[(size_t)BB * TT * VOCAB + i]            = h0fp[16384 + cta * 256 + o];
        out[(size_t)BB * TT * VOCAB + BB * HID + i] = h1fp[16384 + cta * 256 + o];
    }
}

// ---------------------------------------------------------------------------
// fp16 WMMA GEMM (fp32 accum): C[M,N] = A[M,K] @ B[N,K]^T + bias[N]
// Tiles 128x128, k-chunk 64, 2-stage ring fed by cp.async.bulk (1 bulk/row).
// 2 CTAs/SM.
// ---------------------------------------------------------------------------
template <int GATHER, int STORE_GI>
__global__ void __launch_bounds__(256, 2)
gemm_fp16(const __half* __restrict__ A, const int* __restrict__ seq,
          const __half* __restrict__ Bm, const float* __restrict__ bias,
          float* __restrict__ C, int M, int N, int K, int lda)
{
    extern __shared__ __half hsm[];        // 2 stages x (A 128x72 | B 128x72)
    __shared__ float biasS[16][136];
    __shared__ int tokS[128];
    __shared__ __align__(8) unsigned long long mb_[2];

    const int tid = threadIdx.x;
    const int m0 = blockIdx.x * 128;
    const int n0 = blockIdx.y * 128;

    if (GATHER && tid < 128) {
        int m = m0 + tid;
        tokS[tid] = seq[(m & 15) * TT + (m >> 4)];
    }
    for (int i = tid; i < 2048; i += 256)
        biasS[i >> 7][i & 127] = bias[n0 + (i & 127)];

    const uint32_t sb = (uint32_t)__cvta_generic_to_shared(hsm);
    const uint32_t mbb = (uint32_t)__cvta_generic_to_shared(mb_);
    const int KC = K >> 6;

    if (tid == 0) {
        mbar_init(mbb, 1); mbar_init(mbb + 8, 1);
        mbar_expect(mbb, 32768u); mbar_expect(mbb + 8, 32768u);
    }
    __syncthreads();

    auto issue = [&](int kc, int st) {
        const int k0 = kc << 6;
        const int row = tid & 127;
        const uint32_t stb = sb + (uint32_t)st * 36864u;
        if (tid < 128) {
            const __half* src = GATHER ? (A + (size_t)tokS[row] * lda + k0)
                                       : (A + (size_t)(m0 + row) * lda + k0);
            bulk_g2s(stb + row * 144u, src, 128u, mbb + 8u * st);
        } else {
            bulk_g2s(stb + 18432u + row * 144u,
                     Bm + (size_t)(n0 + row) * K + k0, 128u, mbb + 8u * st);
        }
    };
    issue(0, 0);
    issue(1, 1);

    const int warpId = tid >> 5;
    const int wm = warpId >> 1;
    const int wn = warpId & 1;

    wmma::fragment<wmma::accumulator, 16, 16, 16, float> acc[2][4];
#pragma unroll
    for (int mi = 0; mi < 2; mi++)
#pragma unroll
        for (int ni = 0; ni < 4; ni++)
            wmma::load_matrix_sync(acc[mi][ni], &biasS[0][wn * 64 + ni * 16], 136,
                                   wmma::mem_row_major);

    for (int kc = 0; kc < KC; kc++) {
        const int st = kc & 1;
        mbar_wait(mbb + 8u * st, (unsigned)((kc >> 1) & 1));
        const __half* As = hsm + st * 18432;
        const __half* Bs = As + 9216;
#pragma unroll
        for (int ks = 0; ks < 4; ks++) {
            wmma::fragment<wmma::matrix_a, 16, 16, 16, __half, wmma::row_major> a[2];
            wmma::fragment<wmma::matrix_b, 16, 16, 16, __half, wmma::col_major> b[4];
#pragma unroll
            for (int mi = 0; mi < 2; mi++)
                wmma::load_matrix_sync(a[mi], As + (wm * 32 + mi * 16) * 72 + ks * 16, 72);
#pragma unroll
            for (int ni = 0; ni < 4; ni++)
                wmma::load_matrix_sync(b[ni], Bs + (wn * 64 + ni * 16) * 72 + ks * 16, 72);
#pragma unroll
            for (int mi = 0; mi < 2; mi++)
#pragma unroll
                for (int ni = 0; ni < 4; ni++)
                    wmma::mma_sync(acc[mi][ni], a[mi], b[ni], acc[mi][ni]);
        }
        __syncthreads();
        if (kc + 2 < KC) {
            if (tid == 0) mbar_expect(mbb + 8u * st, 32768u);
            __syncthreads();
            issue(kc + 2, st);
        }
    }

#pragma unroll
    for (int mi = 0; mi < 2; mi++)
#pragma unroll
        for (int ni = 0; ni < 4; ni++) {
            int mrow = m0 + wm * 32 + mi * 16;
            int ncol = n0 + wn * 64 + ni * 16;
            if (STORE_GI) {
                int t = mrow >> 4;
                int gate = ncol >> 10;
                int colblk = (ncol & 1023) >> 4;
                wmma::store_matrix_sync(
                    C + (((size_t)t * 64 + colblk) * 3 + gate) * 256,
                    acc[mi][ni], 16, wmma::mem_row_major);
            } else {
                wmma::store_matrix_sync(C + (size_t)mrow * N + ncol,
                                        acc[mi][ni], N, wmma::mem_row_major);
            }
        }
}

// ---------------------------------------------------------------------------
// Persistent fp16 tensor-core GRU. 128 CTAs x 256 thr, 1 CTA/SM.
// k-chunk 128 (8 chunks/step), 3-stage bulk ring. fp32 carry side arrays.
// ---------------------------------------------------------------------------
__global__ void __launch_bounds__(256, 1)
gru_persistent(const float* __restrict__ gi0,
               const __half* __restrict__ wpk0, const float* __restrict__ bhh0,
               const __half* __restrict__ wpk1, const float* __restrict__ bih1,
               const float* __restrict__ bhh1,
               __half* __restrict__ h016, __half* __restrict__ h116,
               float* __restrict__ h0fp, float* __restrict__ h1fp,
               unsigned* __restrict__ cnt)
{
    extern __shared__ char smraw[];
    __half* smA0 = (__half*)smraw;
    __half* smA1 = (__half*)(smraw + A1_OFF);
    __half* ring = (__half*)(smraw + RINGB);
    float*  P    = (float*)(smraw + PARTB);
    float*  GIS  = (float*)(smraw + GIB);
    __shared__ __align__(8) unsigned long long mbars[5];  // 0-2 wring, 3 oper, 4 gi

    const int tid = threadIdx.x;
    const int w = tid >> 5;
    const bool isA = blockIdx.x < 64;
    const int cta = isA ? blockIdx.x : (blockIdx.x - 64);
    const int c0 = cta * 16;
    const int ncw = isA ? 3 : 6;
    const int bb = tid >> 4, jl = tid & 15;
    const int j = c0 + jl;
    volatile unsigned* vc = cnt;

    const __half* wbase = isA ? (wpk0 + (size_t)cta * NCHK * CH0H)
                              : (wpk1 + (size_t)cta * NCHK * CH1H);
    const int chH = isA ? CH0H : CH1H;
    const unsigned chBytes = (unsigned)(chH * 2);

    const uint32_t smb = (uint32_t)__cvta_generic_to_shared(smraw);
    const uint32_t mbb = (uint32_t)__cvta_generic_to_shared(mbars);

    float B0r = 0.f, B0u = 0.f, B0n = 0.f;
    float B1ir = 0.f, B1iu = 0.f, B1in = 0.f, B1hr = 0.f, B1hu = 0.f, B1hn = 0.f;
    if (isA) {
        B0r = bhh0[j]; B0u = bhh0[HID + j]; B0n = bhh0[2 * HID + j];
    } else {
        B1ir = bih1[j]; B1iu = bih1[HID + j]; B1in = bih1[2 * HID + j];
        B1hr = bhh1[j]; B1hu = bhh1[HID + j]; B1hn = bhh1[2 * HID + j];
    }

    if (tid == 0) {
        for (int s = 0; s < 5; s++) mbar_init(mbb + 8 * s, 1);
#pragma unroll
        for (int s = 0; s < 3; s++) {
            mbar_expect(mbb + 8 * s, chBytes);
            bulk_g2s(smb + RINGB + (uint32_t)s * chBytes, wbase + (size_t)s * chH,
                     chBytes, mbb + 8 * s);
        }
        if (isA) {
            mbar_expect(mbb + 32, 3072u);
            bulk_g2s(smb + GIB, gi0 + (size_t)cta * 3 * 256, 3072u, mbb + 32);
        }
    }
    __syncthreads();

    int ws = 0;
    unsigned wpar = 0;
    long gc = 0;
    const long GCMAX = (long)TT * NCHK;
    int hph = 0;

    wmma::fragment<wmma::accumulator, 16, 16, 16, float> acc0, acc1;

    for (int t = 0; t < TT; t++) {
        // ---- handoff spin ----
        if (tid == 0) {
            unsigned sp;
            if (isA) {
                if (t) { sp = 0; while (vc[(t - 1) * CSTRIDE] < 64u) { if (++sp > 16) __nanosleep(32); } }
            } else {
                sp = 0; while (vc[t * CSTRIDE] < 64u) { if (++sp > 16) __nanosleep(32); }
                if (t) { sp = 0; while (vc[(TT + t - 1) * CSTRIDE] < 64u) { if (++sp > 16) __nanosleep(32); } }
            }
        }
        __syncthreads();
        __threadfence();

        // ---- stage fp16 A operands ----
        if (isA) {
            if (t == 0) {
                for (int i = tid; i < 8320; i += 256) ((uint32_t*)smA0)[i] = 0u;
                __syncthreads();
            } else {
                if (tid == 0) mbar_expect(mbb + 24, 32768u);
                __syncthreads();
                if (tid < 16)
                    bulk_g2s(smb + A0_OFF + tid * 2080u,
                             h016 + ((size_t)(t - 1) * BB + tid) * HID, 2048u, mbb + 24);
                mbar_wait(mbb + 24, (unsigned)(hph & 1));
                hph++;
                __syncthreads();
            }
        } else {
            if (tid == 0) mbar_expect(mbb + 24, t > 0 ? 65536u : 32768u);
            __syncthreads();
            if (t == 0) {
                for (int i = tid; i < 8320; i += 256) ((uint32_t*)smA1)[i] = 0u;
            }
            if (tid < 16)
                bulk_g2s(smb + A0_OFF + tid * 2080u,
                         h016 + ((size_t)t * BB + tid) * HID, 2048u, mbb + 24);
            if (t > 0 && tid >= 16 && tid < 32) {
                int b = tid - 16;
                bulk_g2s(smb + A1_OFF + b * 2080u,
                         h116 + ((size_t)b * TT + (t - 1)) * HID, 2048u, mbb + 24);
            }
            mbar_wait(mbb + 24, (unsigned)(hph & 1));
            hph++;
            __syncthreads();
        }

        float hprev = 0.f;
        if (t > 0)
            hprev = (isA ? h0fp : h1fp)[((t + 1) & 1) * 16384 + cta * 256 + tid];

        // ---- K loop over 8 fp16 weight chunks (k=128 each) ----
        wmma::fill_fragment(acc0, 0.f);
        wmma::fill_fragment(acc1, 0.f);
        const __half* Ab = (isA || w < 3) ? smA0 : smA1;

        for (int ch = 0; ch < NCHK; ch++) {
            mbar_wait(mbb + 8 * ws, wpar);
            if (w < ncw) {
                const __half* Ap = Ab + (ch << 7);
                const __half* Bp = ring + ws * chH + w * 16 * WPITCH;
#pragma unroll
                for (int ks = 0; ks < 8; ks++) {
                    wmma::fragment<wmma::matrix_a, 16, 16, 16, __half, wmma::row_major> af;
                    wmma::fragment<wmma::matrix_b, 16, 16, 16, __half, wmma::col_major> bf;
                    wmma::load_matrix_sync(af, Ap + ks * 16, LDHH);
                    wmma::load_matrix_sync(bf, Bp + ks * 16, WPITCH);
                    if (ks & 1) wmma::mma_sync(acc1, af, bf, acc1);
                    else        wmma::mma_sync(acc0, af, bf, acc0);
                }
            }
            __syncthreads();
            if (tid == 0 && gc + 3 < GCMAX) {
                int nch = (int)((gc + 3) & (NCHK - 1));
                mbar_expect(mbb + 8 * ws, chBytes);
                bulk_g2s(smb + RINGB + (uint32_t)ws * chBytes,
                         wbase + (size_t)nch * chH, chBytes, mbb + 8 * ws);
            }
            gc++;
            ws++;
            if (ws == 3) { ws = 0; wpar ^= 1u; }
        }

        // ---- epilogue ----
        if (w < ncw) {
#pragma unroll
            for (int e = 0; e < acc0.num_elements; e++) acc0.x[e] += acc1.x[e];
            wmma::store_matrix_sync(P + w * 256, acc0, 16, wmma::mem_row_major);
        }
        __syncthreads();
        if (isA) mbar_wait(mbb + 32, (unsigned)(t & 1));

        {
            const int o = tid;
            if (isA) {
                const float* gis = GIS + (t & 1) * 768;
                float r = sigmoidf_(gis[o] + P[o] + B0r);
                float u = sigmoidf_(gis[256 + o] + P[256 + o] + B0u);
                float n = tanhf(gis[512 + o] + r * (P[512 + o] + B0n));
                float hnew = (1.f - u) * n + u * hprev;
                h016[((size_t)t * BB + bb) * HID + j] = __float2half_rn(hnew);
                h0fp[(t & 1) * 16384 + cta * 256 + o] = hnew;
            } else {
                float r = sigmoidf_(P[o] + B1ir + P[768 + o] + B1hr);
                float u = sigmoidf_(P[256 + o] + B1iu + P[1024 + o] + B1hu);
                float n = tanhf(P[512 + o] + B1in + r * (P[1280 + o] + B1hn));
                float hnew = (1.f - u) * n + u * hprev;
                h116[((size_t)bb * TT + t) * HID + j] = __float2half_rn(hnew);
                h1fp[(t & 1) * 16384 + cta * 256 + o] = hnew;
            }
        }
        __threadfence();
        __syncthreads();
        if (tid == 0) {
            atomicAdd(&cnt[((isA ? 0 : TT) + t) * CSTRIDE], 1u);
            if (isA && t + 1 < TT) {
                mbar_expect(mbb + 32, 3072u);
                bulk_g2s(smb + GIB + (uint32_t)(((t + 1) & 1) * 3072),
                         gi0 + ((size_t)(t + 1) * 64 + cta) * 3 * 256, 3072u, mbb + 32);
            }
        }
        __syncthreads();
    }
}

extern "C" void kernel_launch(void* const* d_in, const int* in_sizes, int n_in,
                              void* d_out, int out_size)
{
    const int*   seq  = (const int*)d_in[0];
    const float* emb  = (const float*)d_in[1];
    const float* wih0 = (const float*)d_in[2];
    const float* whh0 = (const float*)d_in[3];
    const float* bih0 = (const float*)d_in[4];
    const float* bhh0 = (const float*)d_in[5];
    const float* wih1 = (const float*)d_in[6];
    const float* whh1 = (const float*)d_in[7];
    const float* bih1 = (const float*)d_in[8];
    const float* bhh1 = (const float*)d_in[9];
    const float* wout = (const float*)d_in[10];
    const float* bout = (const float*)d_in[11];
    float* out = (float*)d_out;

    float *gi0, *h0fp, *h1fp; __half *h016, *h116, *wpk0, *wpk1, *emb16, *wih016, *wout16;
    unsigned* cnt;
    cudaGetSymbolAddress((void**)&gi0,    g_gi0);
    cudaGetSymbolAddress((void**)&h016,   g_h016);
    cudaGetSymbolAddress((void**)&h116,   g_h116);
    cudaGetSymbolAddress((void**)&h0fp,   g_h0fp);
    cudaGetSymbolAddress((void**)&h1fp,   g_h1fp);
    cudaGetSymbolAddress((void**)&wpk0,   g_wpk0);
    cudaGetSymbolAddress((void**)&wpk1,   g_wpk1);
    cudaGetSymbolAddress((void**)&emb16,  g_emb16);
    cudaGetSymbolAddress((void**)&wih016, g_wih016);
    cudaGetSymbolAddress((void**)&wout16, g_wout16);
    cudaGetSymbolAddress((void**)&cnt,    g_cnt);

    const int gemm_smem = 73728;
    cudaFuncSetAttribute((const void*)gemm_fp16<1, 1>,
                         cudaFuncAttributeMaxDynamicSharedMemorySize, gemm_smem);
    cudaFuncSetAttribute((const void*)gemm_fp16<0, 0>,
                         cudaFuncAttributeMaxDynamicSharedMemorySize, gemm_smem);
    cudaFuncSetAttribute((const void*)gru_persistent,
                         cudaFuncAttributeMaxDynamicSharedMemorySize, REC_SMEM);

    zero_cnt_k<<<64, 256>>>(cnt);
    f32_to_f16_k<<<4096, 256>>>((const float4*)emb,  (__half2*)emb16,  (long)VOCAB * EMB / 4);
    f32_to_f16_k<<<2048, 256>>>((const float4*)wih0, (__half2*)wih016, (long)H3 * EMB / 4);
    f32_to_f16_k<<<4096, 256>>>((const float4*)wout, (__half2*)wout16, (long)VOCAB * HID / 4);
    repack_k<<<4096, 256>>>(whh0, wih1, whh1, wpk0, wpk1);

    // gi0 packed = gather(emb16) @ wih016^T + b_ih0
    {
        dim3 g(64, H3 / 128);
        gemm_fp16<1, 1><<<g, 256, gemm_smem>>>(emb16, seq, wih016, bih0, gi0,
                                               BB * TT, H3, EMB, EMB);
    }

    gru_persistent<<<128, 256, REC_SMEM>>>(gi0, wpk0, bhh0, wpk1, bih1, bhh1,
                                           h016, h116, h0fp, h1fp, cnt);

    tail_copy_k<<<(BB * HID + 255) / 256, 256>>>(h0fp, h1fp, out);

    // logits = h116 @ wout16^T + b_out
    {
        dim3 g(64, VOCAB / 128);
        gemm_fp16<0, 0><<<g, 256, gemm_smem>>>(h116, nullptr, wout16, bout, out,
                                               BB * TT, VOCAB, HID, HID);
    }
}